// round 1
// baseline (speedup 1.0000x reference)
#include <cuda_runtime.h>
#include <math.h>

#define D_MODEL 1024
#define NHEADS  16
#define DK      64
#define BATCH   2
#define SEQ     2048
#define BS_TOK  (BATCH * SEQ)   // 4096 total tokens

// ---------------------------------------------------------------------------
// Scratch (device globals: no allocation allowed in kernel_launch)
// ---------------------------------------------------------------------------
__device__ float g_Q[BS_TOK * D_MODEL];   // 16.8 MB
__device__ float g_K[BS_TOK * DK];        // 1 MB
__device__ float g_V[BS_TOK * DK];        // 1 MB
__device__ float g_Ctx[BS_TOK * D_MODEL]; // 16.8 MB

// ---------------------------------------------------------------------------
// GEMM: C[M,N] = A[M,K] @ W[K,N] + bias[N]   (all row-major fp32)
// BM=128, BN=64, BK=16, 256 threads, 8x4 per-thread tile.
// M % 128 == 0, N % 64 == 0, K % 16 == 0 for all our shapes.
// ---------------------------------------------------------------------------
__global__ __launch_bounds__(256)
void gemm_bias_kernel(const float* __restrict__ A, const float* __restrict__ W,
                      const float* __restrict__ bias, float* __restrict__ C,
                      int M, int N, int K)
{
    const int BM = 128, BN = 64, BK = 16;
    __shared__ float As[BK][BM + 4];   // transposed A tile, padded
    __shared__ float Bs[BK][BN];       // row-major W tile

    const int t  = threadIdx.x;
    const int tx = t & 15;             // 0..15 -> N direction (4 cols each)
    const int ty = t >> 4;             // 0..15 -> M direction (8 rows each)
    const int m0 = blockIdx.y * BM;
    const int n0 = blockIdx.x * BN;

    float acc[8][4];
    #pragma unroll
    for (int i = 0; i < 8; ++i)
        #pragma unroll
        for (int j = 0; j < 4; ++j) acc[i][j] = 0.0f;

    for (int k0 = 0; k0 < K; k0 += BK) {
        // ---- load A tile (128x16) transposed into As[k][m] ----
        #pragma unroll
        for (int ld = 0; ld < 2; ++ld) {
            int idx = t + ld * 256;          // 0..511
            int r   = idx >> 2;              // 0..127
            int c4  = (idx & 3) * 4;         // 0,4,8,12
            float4 v = *(const float4*)&A[(size_t)(m0 + r) * K + k0 + c4];
            As[c4 + 0][r] = v.x;
            As[c4 + 1][r] = v.y;
            As[c4 + 2][r] = v.z;
            As[c4 + 3][r] = v.w;
        }
        // ---- load W tile (16x64) ----
        {
            int kr = t >> 4;                 // 0..15
            int c4 = (t & 15) * 4;           // 0..60
            *(float4*)&Bs[kr][c4] =
                *(const float4*)&W[(size_t)(k0 + kr) * N + n0 + c4];
        }
        __syncthreads();

        #pragma unroll
        for (int k = 0; k < BK; ++k) {
            float4 a0 = *(const float4*)&As[k][ty * 8];
            float4 a1 = *(const float4*)&As[k][ty * 8 + 4];
            float4 b0 = *(const float4*)&Bs[k][tx * 4];
            float a[8] = {a0.x, a0.y, a0.z, a0.w, a1.x, a1.y, a1.z, a1.w};
            float b[4] = {b0.x, b0.y, b0.z, b0.w};
            #pragma unroll
            for (int i = 0; i < 8; ++i)
                #pragma unroll
                for (int j = 0; j < 4; ++j)
                    acc[i][j] = fmaf(a[i], b[j], acc[i][j]);
        }
        __syncthreads();
    }

    // ---- epilogue: add bias, store ----
    float bb[4];
    #pragma unroll
    for (int j = 0; j < 4; ++j) bb[j] = bias[n0 + tx * 4 + j];
    #pragma unroll
    for (int i = 0; i < 8; ++i) {
        size_t row = (size_t)(m0 + ty * 8 + i);
        float4 out;
        out.x = acc[i][0] + bb[0];
        out.y = acc[i][1] + bb[1];
        out.z = acc[i][2] + bb[2];
        out.w = acc[i][3] + bb[3];
        *(float4*)&C[row * N + n0 + tx * 4] = out;
    }
}

// ---------------------------------------------------------------------------
// Flash attention (MQA, causal). One CTA per (batch, head, 64-row Q tile).
// 256 threads = 16x16 grid; each thread owns a 4x4 patch of the 64x64
// score tile / output tile. Online softmax; all smem accesses are float4.
//
// smem layouts (all padded to 68 floats/row, 68 % 4 == 0 keeps f4 alignment):
//   Qst[d][row] : Q tile transposed   (QK reads qa = f4 over rows)
//   Kst[d][col] : K tile transposed   (QK reads kb = f4 over cols)
//   Vs [c][vc]  : V tile row-major    (PV reads vb = f4 over vcols)
//   Pst[c][row] : P tile transposed   (PV reads pa = f4 over rows)
// ---------------------------------------------------------------------------
#define ATTN_SMEM (4 * 64 * 68 * (int)sizeof(float))   // 69632 B

__global__ __launch_bounds__(256)
void attn_kernel(const float* __restrict__ Q, const float* __restrict__ K,
                 const float* __restrict__ V, float* __restrict__ Ctx)
{
    extern __shared__ float sm[];
    float* Qst = sm;                 // [64][68]
    float* Kst = Qst + 64 * 68;      // [64][68]
    float* Vs  = Kst + 64 * 68;      // [64][68]
    float* Pst = Vs  + 64 * 68;      // [64][68]

    const int t  = threadIdx.x;
    const int tc = t & 15;           // 0..15: col group (cols tc*4..tc*4+3)
    const int tr = t >> 4;           // 0..15: row group (rows tr*4..tr*4+3)
    const int qt = (gridDim.x - 1) - blockIdx.x;  // long blocks first
    const int h  = blockIdx.y;
    const int b  = blockIdx.z;
    const float scale = 0.125f;      // 1/sqrt(64)

    // ---- load Q tile transposed: Qst[d][row] = Q[row][d] ----
    for (int i = t; i < 64 * 16; i += 256) {
        int row = i >> 4;
        int c4  = (i & 15) * 4;
        float4 v = *(const float4*)
            &Q[((size_t)(b * SEQ + qt * 64 + row)) * D_MODEL + h * DK + c4];
        Qst[(c4 + 0) * 68 + row] = v.x;
        Qst[(c4 + 1) * 68 + row] = v.y;
        Qst[(c4 + 2) * 68 + row] = v.z;
        Qst[(c4 + 3) * 68 + row] = v.w;
    }

    float m[4], l[4], o[4][4];
    #pragma unroll
    for (int i = 0; i < 4; ++i) {
        m[i] = -INFINITY;
        l[i] = 0.0f;
        #pragma unroll
        for (int j = 0; j < 4; ++j) o[i][j] = 0.0f;
    }

    for (int j = 0; j <= qt; ++j) {
        __syncthreads();   // protect smem from previous iteration's readers
        // ---- load K (transposed) and V (row-major) tiles ----
        for (int i = t; i < 64 * 16; i += 256) {
            int row = i >> 4;
            int c4  = (i & 15) * 4;
            size_t gb = ((size_t)(b * SEQ + j * 64 + row)) * DK + c4;
            float4 kv = *(const float4*)&K[gb];
            Kst[(c4 + 0) * 68 + row] = kv.x;
            Kst[(c4 + 1) * 68 + row] = kv.y;
            Kst[(c4 + 2) * 68 + row] = kv.z;
            Kst[(c4 + 3) * 68 + row] = kv.w;
            *(float4*)&Vs[row * 68 + c4] = *(const float4*)&V[gb];
        }
        __syncthreads();

        // ---- S = Q K^T ----
        float s[4][4];
        #pragma unroll
        for (int i = 0; i < 4; ++i)
            #pragma unroll
            for (int jj = 0; jj < 4; ++jj) s[i][jj] = 0.0f;

        for (int d = 0; d < 64; ++d) {
            float4 qa = *(const float4*)&Qst[d * 68 + tr * 4];
            float4 kb = *(const float4*)&Kst[d * 68 + tc * 4];
            float a[4] = {qa.x, qa.y, qa.z, qa.w};
            float c[4] = {kb.x, kb.y, kb.z, kb.w};
            #pragma unroll
            for (int i = 0; i < 4; ++i)
                #pragma unroll
                for (int jj = 0; jj < 4; ++jj)
                    s[i][jj] = fmaf(a[i], c[jj], s[i][jj]);
        }

        // ---- scale + causal mask (only the diagonal tile needs it) ----
        const bool diag = (j == qt);
        #pragma unroll
        for (int i = 0; i < 4; ++i)
            #pragma unroll
            for (int jj = 0; jj < 4; ++jj) {
                s[i][jj] *= scale;
                if (diag && (tc * 4 + jj) > (tr * 4 + i)) s[i][jj] = -INFINITY;
            }

        // ---- row max across the 16 col-group lanes ----
        float mt[4];
        #pragma unroll
        for (int i = 0; i < 4; ++i) {
            mt[i] = fmaxf(fmaxf(s[i][0], s[i][1]), fmaxf(s[i][2], s[i][3]));
        }
        #pragma unroll
        for (int off = 1; off < 16; off <<= 1) {
            #pragma unroll
            for (int i = 0; i < 4; ++i)
                mt[i] = fmaxf(mt[i], __shfl_xor_sync(0xffffffffu, mt[i], off));
        }

        // ---- online softmax update ----
        float rs[4];
        #pragma unroll
        for (int i = 0; i < 4; ++i) {
            float mn   = fmaxf(m[i], mt[i]);
            float corr = __expf(m[i] - mn);   // 0 on first tile (m = -inf)
            m[i] = mn;
            l[i] *= corr;
            #pragma unroll
            for (int jj = 0; jj < 4; ++jj) o[i][jj] *= corr;
            rs[i] = 0.0f;
            #pragma unroll
            for (int jj = 0; jj < 4; ++jj) {
                float p = __expf(s[i][jj] - mn);
                s[i][jj] = p;
                rs[i] += p;
            }
        }
        #pragma unroll
        for (int off = 1; off < 16; off <<= 1) {
            #pragma unroll
            for (int i = 0; i < 4; ++i)
                rs[i] += __shfl_xor_sync(0xffffffffu, rs[i], off);
        }
        #pragma unroll
        for (int i = 0; i < 4; ++i) l[i] += rs[i];

        // ---- write P transposed: Pst[col][row] ----
        #pragma unroll
        for (int jj = 0; jj < 4; ++jj) {
            float4 pv;
            pv.x = s[0][jj]; pv.y = s[1][jj]; pv.z = s[2][jj]; pv.w = s[3][jj];
            *(float4*)&Pst[(tc * 4 + jj) * 68 + tr * 4] = pv;
        }
        __syncthreads();

        // ---- O += P V ----
        for (int c = 0; c < 64; ++c) {
            float4 pa = *(const float4*)&Pst[c * 68 + tr * 4];
            float4 vb = *(const float4*)&Vs[c * 68 + tc * 4];
            float a[4] = {pa.x, pa.y, pa.z, pa.w};
            float v[4] = {vb.x, vb.y, vb.z, vb.w};
            #pragma unroll
            for (int i = 0; i < 4; ++i)
                #pragma unroll
                for (int jj = 0; jj < 4; ++jj)
                    o[i][jj] = fmaf(a[i], v[jj], o[i][jj]);
        }
    }

    // ---- normalize + write context (back to [B, S, H*DK] layout) ----
    #pragma unroll
    for (int i = 0; i < 4; ++i) {
        int row = qt * 64 + tr * 4 + i;
        float inv = 1.0f / l[i];
        float4 out;
        out.x = o[i][0] * inv;
        out.y = o[i][1] * inv;
        out.z = o[i][2] * inv;
        out.w = o[i][3] * inv;
        *(float4*)&Ctx[((size_t)(b * SEQ + row)) * D_MODEL + h * DK + tc * 4] = out;
    }
}

// ---------------------------------------------------------------------------
// launch
// ---------------------------------------------------------------------------
extern "C" void kernel_launch(void* const* d_in, const int* in_sizes, int n_in,
                              void* d_out, int out_size)
{
    const float* iq = (const float*)d_in[0];
    const float* ik = (const float*)d_in[1];
    const float* iv = (const float*)d_in[2];
    const float* Wq = (const float*)d_in[3];
    const float* bq = (const float*)d_in[4];
    const float* Wk = (const float*)d_in[5];
    const float* bk = (const float*)d_in[6];
    const float* Wv = (const float*)d_in[7];
    const float* bv = (const float*)d_in[8];
    const float* Wo = (const float*)d_in[9];
    const float* bo = (const float*)d_in[10];
    float* out = (float*)d_out;

    float *pQ, *pK, *pV, *pCtx;
    cudaGetSymbolAddress((void**)&pQ,   g_Q);
    cudaGetSymbolAddress((void**)&pK,   g_K);
    cudaGetSymbolAddress((void**)&pV,   g_V);
    cudaGetSymbolAddress((void**)&pCtx, g_Ctx);

    cudaFuncSetAttribute(attn_kernel,
                         cudaFuncAttributeMaxDynamicSharedMemorySize, ATTN_SMEM);

    // Q projection: [4096,1024] @ [1024,1024]
    gemm_bias_kernel<<<dim3(D_MODEL / 64, BS_TOK / 128), 256>>>(
        iq, Wq, bq, pQ, BS_TOK, D_MODEL, D_MODEL);
    // K projection: [4096,1024] @ [1024,64]
    gemm_bias_kernel<<<dim3(DK / 64, BS_TOK / 128), 256>>>(
        ik, Wk, bk, pK, BS_TOK, DK, D_MODEL);
    // V projection
    gemm_bias_kernel<<<dim3(DK / 64, BS_TOK / 128), 256>>>(
        iv, Wv, bv, pV, BS_TOK, DK, D_MODEL);

    // Attention: grid (q tiles, heads, batch)
    attn_kernel<<<dim3(SEQ / 64, NHEADS, BATCH), 256, ATTN_SMEM>>>(
        pQ, pK, pV, pCtx);

    // Output projection: [4096,1024] @ [1024,1024]
    gemm_bias_kernel<<<dim3(D_MODEL / 64, BS_TOK / 128), 256>>>(
        pCtx, Wo, bo, out, BS_TOK, D_MODEL, D_MODEL);
}

// round 3
// speedup vs baseline: 2.4910x; 2.4910x over previous
#include <cuda_runtime.h>
#include <math.h>
#include <stdint.h>

#define D_MODEL 1024
#define NHEADS  16
#define DK      64
#define BATCH   2
#define SEQ     2048
#define BS_TOK  (BATCH * SEQ)   // 4096 tokens

// ---------------------------------------------------------------------------
// Scratch (device globals: no allocation allowed)
// ---------------------------------------------------------------------------
__device__ float g_Q[BS_TOK * D_MODEL];
__device__ float g_K[BS_TOK * DK];
__device__ float g_V[BS_TOK * DK];
__device__ float g_Ctx[BS_TOK * D_MODEL];

// ---------------------------------------------------------------------------
// tf32 helpers
// ---------------------------------------------------------------------------
__device__ __forceinline__ unsigned f2tf(float x) {
    unsigned r;
    asm("cvt.rna.tf32.f32 %0, %1;" : "=r"(r) : "f"(x));
    return r;
}

// D = A(16x8,row) * B(8x8,col) + D, tf32 in, f32 accum
__device__ __forceinline__ void mma8(float* c, const unsigned* a,
                                     unsigned b0, unsigned b1) {
    asm volatile(
        "mma.sync.aligned.m16n8k8.row.col.f32.tf32.tf32.f32 "
        "{%0,%1,%2,%3}, {%4,%5,%6,%7}, {%8,%9}, {%0,%1,%2,%3};"
        : "+f"(c[0]), "+f"(c[1]), "+f"(c[2]), "+f"(c[3])
        : "r"(a[0]), "r"(a[1]), "r"(a[2]), "r"(a[3]), "r"(b0), "r"(b1));
}

// ---------------------------------------------------------------------------
// Tensor-core GEMM: C[M,N] = A[M,K] @ W[K,N] + bias
// BM=128, BK=32, 256 threads = 8 warps as 2(m) x 4(n), warp tile 64 x WN.
// Fragment layouts (m16n8k8): lane = gid*4+tig (gid=lane/4, tig=lane%4)
//   A: a0=(gid,tig) a1=(gid+8,tig) a2=(gid,tig+4) a3=(gid+8,tig+4)
//   B: b0=(k=tig,n=gid) b1=(k=tig+4,n=gid)
//   C: c0=(gid,2tig) c1=(gid,2tig+1) c2=(gid+8,2tig) c3=(gid+8,2tig+1)
// smem strides 36 / (BN+8) make all fragment LDS conflict-free.
// ---------------------------------------------------------------------------
template<int BN, int WN>
__global__ __launch_bounds__(256)
void gemm_tc(const float* __restrict__ A, const float* __restrict__ W,
             const float* __restrict__ bias, float* __restrict__ C,
             int M, int N, int K)
{
    constexpr int BM = 128, BK = 32;
    constexpr int ASTR = BK + 4;       // 36
    constexpr int BSTR = BN + 8;       // 136 / 72
    constexpr int NF = WN / 8;
    __shared__ unsigned As[BM][ASTR];
    __shared__ unsigned Bs[BK][BSTR];

    const int t = threadIdx.x, lane = t & 31, wp = t >> 5;
    const int wm0 = (wp >> 2) * 64, wn0 = (wp & 3) * WN;
    const int gid = lane >> 2, tig = lane & 3;
    const int m0 = blockIdx.y * BM, n0 = blockIdx.x * BN;

    float acc[4][NF][4];
    #pragma unroll
    for (int mi = 0; mi < 4; ++mi)
        #pragma unroll
        for (int ni = 0; ni < NF; ++ni)
            #pragma unroll
            for (int x = 0; x < 4; ++x) acc[mi][ni][x] = 0.0f;

    for (int k0 = 0; k0 < K; k0 += BK) {
        // stage A tile 128x32 (row-major, tf32-converted)
        #pragma unroll
        for (int i = 0; i < 4; ++i) {
            int idx = t + 256 * i;
            int r = idx >> 3, c4 = (idx & 7) * 4;
            float4 v = *(const float4*)&A[(size_t)(m0 + r) * K + k0 + c4];
            *(uint4*)&As[r][c4] =
                make_uint4(f2tf(v.x), f2tf(v.y), f2tf(v.z), f2tf(v.w));
        }
        // stage B tile 32xBN
        constexpr int BF4 = (BK * BN / 4) / 256;
        #pragma unroll
        for (int i = 0; i < BF4; ++i) {
            int idx = t + 256 * i;
            int r = idx / (BN / 4), c4 = (idx % (BN / 4)) * 4;
            float4 v = *(const float4*)&W[(size_t)(k0 + r) * N + n0 + c4];
            *(uint4*)&Bs[r][c4] =
                make_uint4(f2tf(v.x), f2tf(v.y), f2tf(v.z), f2tf(v.w));
        }
        __syncthreads();

        #pragma unroll
        for (int kk = 0; kk < 4; ++kk) {
            const int kc = kk * 8 + tig;
            unsigned a[4][4];
            #pragma unroll
            for (int mi = 0; mi < 4; ++mi) {
                int r = wm0 + mi * 16 + gid;
                a[mi][0] = As[r][kc];
                a[mi][1] = As[r + 8][kc];
                a[mi][2] = As[r][kc + 4];
                a[mi][3] = As[r + 8][kc + 4];
            }
            #pragma unroll
            for (int ni = 0; ni < NF; ++ni) {
                int n = wn0 + ni * 8 + gid;
                unsigned b0 = Bs[kc][n];
                unsigned b1 = Bs[kc + 4][n];
                #pragma unroll
                for (int mi = 0; mi < 4; ++mi) mma8(acc[mi][ni], a[mi], b0, b1);
            }
        }
        __syncthreads();
    }

    // epilogue: bias + store (float2 per C-frag half)
    #pragma unroll
    for (int mi = 0; mi < 4; ++mi) {
        int r = m0 + wm0 + mi * 16 + gid;
        #pragma unroll
        for (int ni = 0; ni < NF; ++ni) {
            int c = n0 + wn0 + ni * 8 + 2 * tig;
            float bb0 = bias[c], bb1 = bias[c + 1];
            *(float2*)&C[(size_t)r * N + c] =
                make_float2(acc[mi][ni][0] + bb0, acc[mi][ni][1] + bb1);
            *(float2*)&C[(size_t)(r + 8) * N + c] =
                make_float2(acc[mi][ni][2] + bb0, acc[mi][ni][3] + bb1);
        }
    }
}

// ---------------------------------------------------------------------------
// Tensor-core flash attention (MQA, causal).
// CTA: 128 threads = 4 warps; Q tile 64 rows, warp owns 16 rows.
// Q frags register-resident (scaled by 1/8 at tf32 convert).
// smem: Ks[kpos][d], Vt[dv][kpos], Ps[row][col] (Q staging, then P),
// all stride 68 -> every fragment LDS is bank-conflict-free.
// P smem round-trip is warp-private (own 16 rows) -> __syncwarp only.
// ---------------------------------------------------------------------------
#define AS 68
#define ATTN_SMEM_TC (3 * 64 * AS * 4)   // 52224 B

__global__ __launch_bounds__(128)
void attn_tc(const float* __restrict__ Q, const float* __restrict__ K,
             const float* __restrict__ V, float* __restrict__ Ctx)
{
    extern __shared__ unsigned smu[];
    unsigned* Ks = smu;                 // [64][AS] : [kpos][d]
    unsigned* Vt = smu + 64 * AS;       // [64][AS] : [dv][kpos]
    unsigned* Ps = smu + 2 * 64 * AS;   // [64][AS] : [row][col]

    const int t = threadIdx.x, lane = t & 31, w = t >> 5;
    const int gid = lane >> 2, tig = lane & 3;
    const int qt = (int)(gridDim.x - 1) - (int)blockIdx.x;  // long blocks first
    const int h = blockIdx.y, b = blockIdx.z;

    // stage Q (pre-scaled) into Ps
    for (int i = t; i < 64 * 16; i += 128) {
        int row = i >> 4, c4 = (i & 15) * 4;
        float4 v = *(const float4*)
            &Q[((size_t)(b * SEQ + qt * 64 + row)) * D_MODEL + h * DK + c4];
        *(uint4*)&Ps[row * AS + c4] =
            make_uint4(f2tf(0.125f * v.x), f2tf(0.125f * v.y),
                       f2tf(0.125f * v.z), f2tf(0.125f * v.w));
    }
    __syncthreads();

    unsigned Qa[8][4];
    {
        int r0 = 16 * w + gid;
        #pragma unroll
        for (int kf = 0; kf < 8; ++kf) {
            int kc = kf * 8 + tig;
            Qa[kf][0] = Ps[r0 * AS + kc];
            Qa[kf][1] = Ps[(r0 + 8) * AS + kc];
            Qa[kf][2] = Ps[r0 * AS + kc + 4];
            Qa[kf][3] = Ps[(r0 + 8) * AS + kc + 4];
        }
    }

    float m0 = -INFINITY, m1 = -INFINITY, l0 = 0.0f, l1 = 0.0f;
    float O[8][4];
    #pragma unroll
    for (int nf = 0; nf < 8; ++nf)
        #pragma unroll
        for (int x = 0; x < 4; ++x) O[nf][x] = 0.0f;

    for (int j = 0; j <= qt; ++j) {
        __syncthreads();   // prev iter's smem readers done
        // stage K (row-major) and V (transposed)
        for (int i = t; i < 64 * 16; i += 128) {
            int row = i >> 4, c4 = (i & 15) * 4;
            size_t g = ((size_t)(b * SEQ + j * 64 + row)) * DK + c4;
            float4 kv = *(const float4*)&K[g];
            *(uint4*)&Ks[row * AS + c4] =
                make_uint4(f2tf(kv.x), f2tf(kv.y), f2tf(kv.z), f2tf(kv.w));
            float4 vv = *(const float4*)&V[g];
            Vt[(c4 + 0) * AS + row] = f2tf(vv.x);
            Vt[(c4 + 1) * AS + row] = f2tf(vv.y);
            Vt[(c4 + 2) * AS + row] = f2tf(vv.z);
            Vt[(c4 + 3) * AS + row] = f2tf(vv.w);
        }
        __syncthreads();

        // S = (Q/8) K^T  : warp computes 16x64
        float S[8][4];
        #pragma unroll
        for (int nf = 0; nf < 8; ++nf)
            #pragma unroll
            for (int x = 0; x < 4; ++x) S[nf][x] = 0.0f;
        #pragma unroll
        for (int kf = 0; kf < 8; ++kf) {
            const int kc = kf * 8 + tig;
            #pragma unroll
            for (int nf = 0; nf < 8; ++nf) {
                unsigned b0 = Ks[(nf * 8 + gid) * AS + kc];
                unsigned b1 = Ks[(nf * 8 + gid) * AS + kc + 4];
                mma8(S[nf], Qa[kf], b0, b1);
            }
        }

        // causal mask on diagonal tile
        if (j == qt) {
            int qr = qt * 64 + 16 * w + gid;
            #pragma unroll
            for (int nf = 0; nf < 8; ++nf) {
                int c0 = j * 64 + nf * 8 + 2 * tig;
                if (c0     > qr)     S[nf][0] = -INFINITY;
                if (c0 + 1 > qr)     S[nf][1] = -INFINITY;
                if (c0     > qr + 8) S[nf][2] = -INFINITY;
                if (c0 + 1 > qr + 8) S[nf][3] = -INFINITY;
            }
        }

        // row max (rows gid / gid+8; reduce over quad lanes)
        float mx0 = -INFINITY, mx1 = -INFINITY;
        #pragma unroll
        for (int nf = 0; nf < 8; ++nf) {
            mx0 = fmaxf(mx0, fmaxf(S[nf][0], S[nf][1]));
            mx1 = fmaxf(mx1, fmaxf(S[nf][2], S[nf][3]));
        }
        mx0 = fmaxf(mx0, __shfl_xor_sync(0xffffffffu, mx0, 1));
        mx0 = fmaxf(mx0, __shfl_xor_sync(0xffffffffu, mx0, 2));
        mx1 = fmaxf(mx1, __shfl_xor_sync(0xffffffffu, mx1, 1));
        mx1 = fmaxf(mx1, __shfl_xor_sync(0xffffffffu, mx1, 2));

        float mn0 = fmaxf(m0, mx0), mn1 = fmaxf(m1, mx1);
        float cr0 = __expf(m0 - mn0), cr1 = __expf(m1 - mn1);
        m0 = mn0; m1 = mn1;

        float rs0 = 0.0f, rs1 = 0.0f;
        #pragma unroll
        for (int nf = 0; nf < 8; ++nf) {
            S[nf][0] = __expf(S[nf][0] - mn0);
            S[nf][1] = __expf(S[nf][1] - mn0);
            S[nf][2] = __expf(S[nf][2] - mn1);
            S[nf][3] = __expf(S[nf][3] - mn1);
            rs0 += S[nf][0] + S[nf][1];
            rs1 += S[nf][2] + S[nf][3];
        }
        rs0 += __shfl_xor_sync(0xffffffffu, rs0, 1);
        rs0 += __shfl_xor_sync(0xffffffffu, rs0, 2);
        rs1 += __shfl_xor_sync(0xffffffffu, rs1, 1);
        rs1 += __shfl_xor_sync(0xffffffffu, rs1, 2);
        l0 = l0 * cr0 + rs0;
        l1 = l1 * cr1 + rs1;
        #pragma unroll
        for (int nf = 0; nf < 8; ++nf) {
            O[nf][0] *= cr0; O[nf][1] *= cr0;
            O[nf][2] *= cr1; O[nf][3] *= cr1;
        }

        // P -> smem (warp-private rows), then PV
        const int pr = 16 * w + gid;
        #pragma unroll
        for (int nf = 0; nf < 8; ++nf) {
            int pc = nf * 8 + 2 * tig;
            *(uint2*)&Ps[pr * AS + pc] =
                make_uint2(f2tf(S[nf][0]), f2tf(S[nf][1]));
            *(uint2*)&Ps[(pr + 8) * AS + pc] =
                make_uint2(f2tf(S[nf][2]), f2tf(S[nf][3]));
        }
        __syncwarp();
        #pragma unroll
        for (int kf = 0; kf < 8; ++kf) {
            const int kc = kf * 8 + tig;
            unsigned pa[4];
            pa[0] = Ps[pr * AS + kc];
            pa[1] = Ps[(pr + 8) * AS + kc];
            pa[2] = Ps[pr * AS + kc + 4];
            pa[3] = Ps[(pr + 8) * AS + kc + 4];
            #pragma unroll
            for (int nf = 0; nf < 8; ++nf) {
                unsigned b0 = Vt[(nf * 8 + gid) * AS + kc];
                unsigned b1 = Vt[(nf * 8 + gid) * AS + kc + 4];
                mma8(O[nf], pa, b0, b1);
            }
        }
    }

    // normalize + write context
    float inv0 = 1.0f / l0, inv1 = 1.0f / l1;
    int r0 = qt * 64 + 16 * w + gid;
    #pragma unroll
    for (int nf = 0; nf < 8; ++nf) {
        int c = h * DK + nf * 8 + 2 * tig;
        *(float2*)&Ctx[((size_t)(b * SEQ + r0)) * D_MODEL + c] =
            make_float2(O[nf][0] * inv0, O[nf][1] * inv0);
        *(float2*)&Ctx[((size_t)(b * SEQ + r0 + 8)) * D_MODEL + c] =
            make_float2(O[nf][2] * inv1, O[nf][3] * inv1);
    }
}

// ---------------------------------------------------------------------------
// launch
// ---------------------------------------------------------------------------
extern "C" void kernel_launch(void* const* d_in, const int* in_sizes, int n_in,
                              void* d_out, int out_size)
{
    const float* iq = (const float*)d_in[0];
    const float* ik = (const float*)d_in[1];
    const float* iv = (const float*)d_in[2];
    const float* Wq = (const float*)d_in[3];
    const float* bq = (const float*)d_in[4];
    const float* Wk = (const float*)d_in[5];
    const float* bk = (const float*)d_in[6];
    const float* Wv = (const float*)d_in[7];
    const float* bv = (const float*)d_in[8];
    const float* Wo = (const float*)d_in[9];
    const float* bo = (const float*)d_in[10];
    float* out = (float*)d_out;

    float *pQ, *pK, *pV, *pCtx;
    cudaGetSymbolAddress((void**)&pQ,   g_Q);
    cudaGetSymbolAddress((void**)&pK,   g_K);
    cudaGetSymbolAddress((void**)&pV,   g_V);
    cudaGetSymbolAddress((void**)&pCtx, g_Ctx);

    cudaFuncSetAttribute(attn_tc,
                         cudaFuncAttributeMaxDynamicSharedMemorySize,
                         ATTN_SMEM_TC);

    // Q projection: [4096,1024] = [4096,1024] @ [1024,1024]
    gemm_tc<128, 32><<<dim3(D_MODEL / 128, BS_TOK / 128), 256>>>(
        iq, Wq, bq, pQ, BS_TOK, D_MODEL, D_MODEL);
    // K projection: [4096,64]
    gemm_tc<64, 16><<<dim3(1, BS_TOK / 128), 256>>>(
        ik, Wk, bk, pK, BS_TOK, DK, D_MODEL);
    // V projection: [4096,64]
    gemm_tc<64, 16><<<dim3(1, BS_TOK / 128), 256>>>(
        iv, Wv, bv, pV, BS_TOK, DK, D_MODEL);

    // Attention
    attn_tc<<<dim3(SEQ / 64, NHEADS, BATCH), 128, ATTN_SMEM_TC>>>(
        pQ, pK, pV, pCtx);

    // Output projection: [4096,1024]
    gemm_tc<128, 32><<<dim3(D_MODEL / 128, BS_TOK / 128), 256>>>(
        pCtx, Wo, bo, out, BS_TOK, D_MODEL, D_MODEL);
}

// round 4
// speedup vs baseline: 2.8860x; 1.1586x over previous
#include <cuda_runtime.h>
#include <math.h>
#include <stdint.h>

#define D_MODEL 1024
#define NHEADS  16
#define DK      64
#define BATCH   2
#define SEQ     2048
#define BS_TOK  (BATCH * SEQ)   // 4096 tokens

// ---------------------------------------------------------------------------
// Scratch (device globals: no allocation allowed)
// ---------------------------------------------------------------------------
__device__ float g_Q[BS_TOK * D_MODEL];
__device__ float g_K[BS_TOK * DK];
__device__ float g_V[BS_TOK * DK];
__device__ float g_Ctx[BS_TOK * D_MODEL];

// ---------------------------------------------------------------------------
// tf32 helpers
// ---------------------------------------------------------------------------
__device__ __forceinline__ unsigned f2tf(float x) {
    unsigned r;
    asm("cvt.rna.tf32.f32 %0, %1;" : "=r"(r) : "f"(x));
    return r;
}

// D = A(16x8,row) * B(8x8,col) + D, tf32 in, f32 accum
__device__ __forceinline__ void mma8(float* c, const unsigned* a,
                                     unsigned b0, unsigned b1) {
    asm volatile(
        "mma.sync.aligned.m16n8k8.row.col.f32.tf32.tf32.f32 "
        "{%0,%1,%2,%3}, {%4,%5,%6,%7}, {%8,%9}, {%0,%1,%2,%3};"
        : "+f"(c[0]), "+f"(c[1]), "+f"(c[2]), "+f"(c[3])
        : "r"(a[0]), "r"(a[1]), "r"(a[2]), "r"(a[3]), "r"(b0), "r"(b1));
}

// ---------------------------------------------------------------------------
// Tensor-core GEMM, double-buffered: C[M,N] = A[M,K] @ W[K,N] + bias
// BM=128, BK=32, 256 threads = 8 warps as 2(m) x 4(n), warp tile 64 x WN.
// Software pipeline: global loads of tile k+1 (regs) overlap MMAs of tile k;
// regs -> other smem buffer after compute; one __syncthreads per K-step.
// Dynamic smem: [As0 | As1 | Bs0 | Bs1], strides 36/(BN+8) conflict-free.
// ---------------------------------------------------------------------------
template<int BN, int WN>
__global__ __launch_bounds__(256)
void gemm_tc(const float* __restrict__ A, const float* __restrict__ W,
             const float* __restrict__ bias, float* __restrict__ C,
             int M, int N, int K)
{
    constexpr int BM = 128, BK = 32;
    constexpr int ASTR = BK + 4;       // 36
    constexpr int BSTR = BN + 8;       // 136 / 72
    constexpr int NF = WN / 8;
    constexpr int ABUF = BM * ASTR;
    constexpr int BBUF = BK * BSTR;
    constexpr int BF4 = (BK * BN / 4) / 256;
    extern __shared__ unsigned smg[];

    const int t = threadIdx.x, lane = t & 31, wp = t >> 5;
    const int wm0 = (wp >> 2) * 64, wn0 = (wp & 3) * WN;
    const int gid = lane >> 2, tig = lane & 3;
    const int m0 = blockIdx.y * BM, n0 = blockIdx.x * BN;

    float4 ra[4], rb[BF4];

    // ---- prologue: load + stage tile 0 ----
    #pragma unroll
    for (int i = 0; i < 4; ++i) {
        int idx = t + 256 * i;
        int r = idx >> 3, c4 = (idx & 7) * 4;
        ra[i] = *(const float4*)&A[(size_t)(m0 + r) * K + c4];
    }
    #pragma unroll
    for (int i = 0; i < BF4; ++i) {
        int idx = t + 256 * i;
        int r = idx / (BN / 4), c4 = (idx % (BN / 4)) * 4;
        rb[i] = *(const float4*)&W[(size_t)r * N + n0 + c4];
    }
    #pragma unroll
    for (int i = 0; i < 4; ++i) {
        int idx = t + 256 * i;
        int r = idx >> 3, c4 = (idx & 7) * 4;
        *(uint4*)&smg[r * ASTR + c4] =
            make_uint4(f2tf(ra[i].x), f2tf(ra[i].y), f2tf(ra[i].z), f2tf(ra[i].w));
    }
    #pragma unroll
    for (int i = 0; i < BF4; ++i) {
        int idx = t + 256 * i;
        int r = idx / (BN / 4), c4 = (idx % (BN / 4)) * 4;
        *(uint4*)&smg[2 * ABUF + r * BSTR + c4] =
            make_uint4(f2tf(rb[i].x), f2tf(rb[i].y), f2tf(rb[i].z), f2tf(rb[i].w));
    }
    __syncthreads();

    float acc[4][NF][4];
    #pragma unroll
    for (int mi = 0; mi < 4; ++mi)
        #pragma unroll
        for (int ni = 0; ni < NF; ++ni)
            #pragma unroll
            for (int x = 0; x < 4; ++x) acc[mi][ni][x] = 0.0f;

    int cur = 0;
    for (int k0 = 0; k0 < K; k0 += BK) {
        unsigned* As = smg + cur * ABUF;
        unsigned* Bs = smg + 2 * ABUF + cur * BBUF;
        const bool more = (k0 + BK) < K;

        // ---- prefetch next tile into regs ----
        if (more) {
            #pragma unroll
            for (int i = 0; i < 4; ++i) {
                int idx = t + 256 * i;
                int r = idx >> 3, c4 = (idx & 7) * 4;
                ra[i] = *(const float4*)&A[(size_t)(m0 + r) * K + k0 + BK + c4];
            }
            #pragma unroll
            for (int i = 0; i < BF4; ++i) {
                int idx = t + 256 * i;
                int r = idx / (BN / 4), c4 = (idx % (BN / 4)) * 4;
                rb[i] = *(const float4*)&W[(size_t)(k0 + BK + r) * N + n0 + c4];
            }
        }

        // ---- MMAs on current tile ----
        #pragma unroll
        for (int kk = 0; kk < 4; ++kk) {
            const int kc = kk * 8 + tig;
            unsigned a[4][4];
            #pragma unroll
            for (int mi = 0; mi < 4; ++mi) {
                int r = wm0 + mi * 16 + gid;
                a[mi][0] = As[r * ASTR + kc];
                a[mi][1] = As[(r + 8) * ASTR + kc];
                a[mi][2] = As[r * ASTR + kc + 4];
                a[mi][3] = As[(r + 8) * ASTR + kc + 4];
            }
            #pragma unroll
            for (int ni = 0; ni < NF; ++ni) {
                int n = wn0 + ni * 8 + gid;
                unsigned b0 = Bs[kc * BSTR + n];
                unsigned b1 = Bs[(kc + 4) * BSTR + n];
                #pragma unroll
                for (int mi = 0; mi < 4; ++mi) mma8(acc[mi][ni], a[mi], b0, b1);
            }
        }

        // ---- stage prefetched regs into the other buffer ----
        if (more) {
            unsigned* An = smg + (cur ^ 1) * ABUF;
            unsigned* Bn = smg + 2 * ABUF + (cur ^ 1) * BBUF;
            #pragma unroll
            for (int i = 0; i < 4; ++i) {
                int idx = t + 256 * i;
                int r = idx >> 3, c4 = (idx & 7) * 4;
                *(uint4*)&An[r * ASTR + c4] =
                    make_uint4(f2tf(ra[i].x), f2tf(ra[i].y),
                               f2tf(ra[i].z), f2tf(ra[i].w));
            }
            #pragma unroll
            for (int i = 0; i < BF4; ++i) {
                int idx = t + 256 * i;
                int r = idx / (BN / 4), c4 = (idx % (BN / 4)) * 4;
                *(uint4*)&Bn[r * BSTR + c4] =
                    make_uint4(f2tf(rb[i].x), f2tf(rb[i].y),
                               f2tf(rb[i].z), f2tf(rb[i].w));
            }
        }
        __syncthreads();
        cur ^= 1;
    }

    // ---- epilogue: bias + store ----
    #pragma unroll
    for (int mi = 0; mi < 4; ++mi) {
        int r = m0 + wm0 + mi * 16 + gid;
        #pragma unroll
        for (int ni = 0; ni < NF; ++ni) {
            int c = n0 + wn0 + ni * 8 + 2 * tig;
            float bb0 = bias[c], bb1 = bias[c + 1];
            *(float2*)&C[(size_t)r * N + c] =
                make_float2(acc[mi][ni][0] + bb0, acc[mi][ni][1] + bb1);
            *(float2*)&C[(size_t)(r + 8) * N + c] =
                make_float2(acc[mi][ni][2] + bb0, acc[mi][ni][3] + bb1);
        }
    }
}

#define GEMM_SMEM_128 ((2 * 128 * 36 + 2 * 32 * 136) * 4)   // 71680
#define GEMM_SMEM_64  ((2 * 128 * 36 + 2 * 32 * 72) * 4)    // 55296

// ---------------------------------------------------------------------------
// Tensor-core flash attention (MQA, causal), 2 heads per CTA.
// 256 threads = 8 warps: warps 0-3 -> head h0, warps 4-7 -> head h1,
// sharing the K/V tiles (staging traffic halved vs 1 head/CTA).
// Q frags register-resident (scaled 1/8 at tf32 convert).
// smem: Ks[kpos][d] (row-major), Vs[kpos][dv] (row-major, conflict-free
// writes; PV B reads ~1.6-way), Ps[128 rows][col] (Q staging then P).
// P round-trip warp-private -> __syncwarp only.
// ---------------------------------------------------------------------------
#define AS 68
#define ATTN_SMEM_TC ((64 + 64 + 128) * AS * 4)   // 69632 B

__global__ __launch_bounds__(256)
void attn_tc(const float* __restrict__ Q, const float* __restrict__ K,
             const float* __restrict__ V, float* __restrict__ Ctx)
{
    extern __shared__ unsigned smu[];
    unsigned* Ks = smu;                  // [64][AS]  : [kpos][d]
    unsigned* Vs = smu + 64 * AS;        // [64][AS]  : [kpos][dv]
    unsigned* Ps = smu + 2 * 64 * AS;    // [128][AS] : [row][col]

    const int t = threadIdx.x, lane = t & 31, w = t >> 5;
    const int hw = w & 3;                // warp within head group
    const int gid = lane >> 2, tig = lane & 3;
    const int qt = (int)(gridDim.x - 1) - (int)blockIdx.x;  // long blocks first
    const int h = blockIdx.y * 2 + (w >> 2);
    const int b = blockIdx.z;

    // ---- stage Q for both heads (pre-scaled), rows 0-63 = h0, 64-127 = h1 ----
    for (int i = t; i < 128 * 16; i += 256) {
        int row = i >> 4, c4 = (i & 15) * 4;
        int hh = blockIdx.y * 2 + (row >> 6);
        int qrow = row & 63;
        float4 v = *(const float4*)
            &Q[((size_t)(b * SEQ + qt * 64 + qrow)) * D_MODEL + hh * DK + c4];
        *(uint4*)&Ps[row * AS + c4] =
            make_uint4(f2tf(0.125f * v.x), f2tf(0.125f * v.y),
                       f2tf(0.125f * v.z), f2tf(0.125f * v.w));
    }
    __syncthreads();

    unsigned Qa[8][4];
    {
        int r0 = 16 * w + gid;           // = headlocal*64 + hw*16 + gid
        #pragma unroll
        for (int kf = 0; kf < 8; ++kf) {
            int kc = kf * 8 + tig;
            Qa[kf][0] = Ps[r0 * AS + kc];
            Qa[kf][1] = Ps[(r0 + 8) * AS + kc];
            Qa[kf][2] = Ps[r0 * AS + kc + 4];
            Qa[kf][3] = Ps[(r0 + 8) * AS + kc + 4];
        }
    }

    float m0 = -INFINITY, m1 = -INFINITY, l0 = 0.0f, l1 = 0.0f;
    float O[8][4];
    #pragma unroll
    for (int nf = 0; nf < 8; ++nf)
        #pragma unroll
        for (int x = 0; x < 4; ++x) O[nf][x] = 0.0f;

    for (int j = 0; j <= qt; ++j) {
        __syncthreads();   // all warps done reading Ks/Vs of prev iter
        // ---- stage K and V (both row-major, conflict-free f4 stores) ----
        for (int i = t; i < 64 * 16; i += 256) {
            int row = i >> 4, c4 = (i & 15) * 4;
            size_t g = ((size_t)(b * SEQ + j * 64 + row)) * DK + c4;
            float4 kv = *(const float4*)&K[g];
            *(uint4*)&Ks[row * AS + c4] =
                make_uint4(f2tf(kv.x), f2tf(kv.y), f2tf(kv.z), f2tf(kv.w));
            float4 vv = *(const float4*)&V[g];
            *(uint4*)&Vs[row * AS + c4] =
                make_uint4(f2tf(vv.x), f2tf(vv.y), f2tf(vv.z), f2tf(vv.w));
        }
        __syncthreads();

        // ---- S = (Q/8) K^T : warp computes 16x64 ----
        float S[8][4];
        #pragma unroll
        for (int nf = 0; nf < 8; ++nf)
            #pragma unroll
            for (int x = 0; x < 4; ++x) S[nf][x] = 0.0f;
        #pragma unroll
        for (int kf = 0; kf < 8; ++kf) {
            const int kc = kf * 8 + tig;
            #pragma unroll
            for (int nf = 0; nf < 8; ++nf) {
                unsigned b0 = Ks[(nf * 8 + gid) * AS + kc];
                unsigned b1 = Ks[(nf * 8 + gid) * AS + kc + 4];
                mma8(S[nf], Qa[kf], b0, b1);
            }
        }

        // ---- causal mask on diagonal tile ----
        if (j == qt) {
            int qr = qt * 64 + 16 * hw + gid;
            #pragma unroll
            for (int nf = 0; nf < 8; ++nf) {
                int c0 = j * 64 + nf * 8 + 2 * tig;
                if (c0     > qr)     S[nf][0] = -INFINITY;
                if (c0 + 1 > qr)     S[nf][1] = -INFINITY;
                if (c0     > qr + 8) S[nf][2] = -INFINITY;
                if (c0 + 1 > qr + 8) S[nf][3] = -INFINITY;
            }
        }

        // ---- row max (rows gid / gid+8; reduce over quad lanes) ----
        float mx0 = -INFINITY, mx1 = -INFINITY;
        #pragma unroll
        for (int nf = 0; nf < 8; ++nf) {
            mx0 = fmaxf(mx0, fmaxf(S[nf][0], S[nf][1]));
            mx1 = fmaxf(mx1, fmaxf(S[nf][2], S[nf][3]));
        }
        mx0 = fmaxf(mx0, __shfl_xor_sync(0xffffffffu, mx0, 1));
        mx0 = fmaxf(mx0, __shfl_xor_sync(0xffffffffu, mx0, 2));
        mx1 = fmaxf(mx1, __shfl_xor_sync(0xffffffffu, mx1, 1));
        mx1 = fmaxf(mx1, __shfl_xor_sync(0xffffffffu, mx1, 2));

        float mn0 = fmaxf(m0, mx0), mn1 = fmaxf(m1, mx1);
        float cr0 = __expf(m0 - mn0), cr1 = __expf(m1 - mn1);
        m0 = mn0; m1 = mn1;

        float rs0 = 0.0f, rs1 = 0.0f;
        #pragma unroll
        for (int nf = 0; nf < 8; ++nf) {
            S[nf][0] = __expf(S[nf][0] - mn0);
            S[nf][1] = __expf(S[nf][1] - mn0);
            S[nf][2] = __expf(S[nf][2] - mn1);
            S[nf][3] = __expf(S[nf][3] - mn1);
            rs0 += S[nf][0] + S[nf][1];
            rs1 += S[nf][2] + S[nf][3];
        }
        rs0 += __shfl_xor_sync(0xffffffffu, rs0, 1);
        rs0 += __shfl_xor_sync(0xffffffffu, rs0, 2);
        rs1 += __shfl_xor_sync(0xffffffffu, rs1, 1);
        rs1 += __shfl_xor_sync(0xffffffffu, rs1, 2);
        l0 = l0 * cr0 + rs0;
        l1 = l1 * cr1 + rs1;
        #pragma unroll
        for (int nf = 0; nf < 8; ++nf) {
            O[nf][0] *= cr0; O[nf][1] *= cr0;
            O[nf][2] *= cr1; O[nf][3] *= cr1;
        }

        // ---- P -> smem (warp-private rows), then O += P V ----
        const int pr = 16 * w + gid;
        #pragma unroll
        for (int nf = 0; nf < 8; ++nf) {
            int pc = nf * 8 + 2 * tig;
            *(uint2*)&Ps[pr * AS + pc] =
                make_uint2(f2tf(S[nf][0]), f2tf(S[nf][1]));
            *(uint2*)&Ps[(pr + 8) * AS + pc] =
                make_uint2(f2tf(S[nf][2]), f2tf(S[nf][3]));
        }
        __syncwarp();
        #pragma unroll
        for (int kf = 0; kf < 8; ++kf) {
            const int kc = kf * 8 + tig;
            unsigned pa[4];
            pa[0] = Ps[pr * AS + kc];
            pa[1] = Ps[(pr + 8) * AS + kc];
            pa[2] = Ps[pr * AS + kc + 4];
            pa[3] = Ps[(pr + 8) * AS + kc + 4];
            #pragma unroll
            for (int nf = 0; nf < 8; ++nf) {
                unsigned b0 = Vs[kc * AS + nf * 8 + gid];
                unsigned b1 = Vs[(kc + 4) * AS + nf * 8 + gid];
                mma8(O[nf], pa, b0, b1);
            }
        }
    }

    // ---- normalize + write context ----
    float inv0 = 1.0f / l0, inv1 = 1.0f / l1;
    int r0 = qt * 64 + 16 * hw + gid;
    #pragma unroll
    for (int nf = 0; nf < 8; ++nf) {
        int c = h * DK + nf * 8 + 2 * tig;
        *(float2*)&Ctx[((size_t)(b * SEQ + r0)) * D_MODEL + c] =
            make_float2(O[nf][0] * inv0, O[nf][1] * inv0);
        *(float2*)&Ctx[((size_t)(b * SEQ + r0 + 8)) * D_MODEL + c] =
            make_float2(O[nf][2] * inv1, O[nf][3] * inv1);
    }
}

// ---------------------------------------------------------------------------
// launch
// ---------------------------------------------------------------------------
extern "C" void kernel_launch(void* const* d_in, const int* in_sizes, int n_in,
                              void* d_out, int out_size)
{
    const float* iq = (const float*)d_in[0];
    const float* ik = (const float*)d_in[1];
    const float* iv = (const float*)d_in[2];
    const float* Wq = (const float*)d_in[3];
    const float* bq = (const float*)d_in[4];
    const float* Wk = (const float*)d_in[5];
    const float* bk = (const float*)d_in[6];
    const float* Wv = (const float*)d_in[7];
    const float* bv = (const float*)d_in[8];
    const float* Wo = (const float*)d_in[9];
    const float* bo = (const float*)d_in[10];
    float* out = (float*)d_out;

    float *pQ, *pK, *pV, *pCtx;
    cudaGetSymbolAddress((void**)&pQ,   g_Q);
    cudaGetSymbolAddress((void**)&pK,   g_K);
    cudaGetSymbolAddress((void**)&pV,   g_V);
    cudaGetSymbolAddress((void**)&pCtx, g_Ctx);

    cudaFuncSetAttribute(gemm_tc<128, 32>,
                         cudaFuncAttributeMaxDynamicSharedMemorySize,
                         GEMM_SMEM_128);
    cudaFuncSetAttribute(gemm_tc<64, 16>,
                         cudaFuncAttributeMaxDynamicSharedMemorySize,
                         GEMM_SMEM_64);
    cudaFuncSetAttribute(attn_tc,
                         cudaFuncAttributeMaxDynamicSharedMemorySize,
                         ATTN_SMEM_TC);

    // Q projection: [4096,1024] = [4096,1024] @ [1024,1024]
    gemm_tc<128, 32><<<dim3(D_MODEL / 128, BS_TOK / 128), 256, GEMM_SMEM_128>>>(
        iq, Wq, bq, pQ, BS_TOK, D_MODEL, D_MODEL);
    // K projection: [4096,64]
    gemm_tc<64, 16><<<dim3(1, BS_TOK / 128), 256, GEMM_SMEM_64>>>(
        ik, Wk, bk, pK, BS_TOK, DK, D_MODEL);
    // V projection: [4096,64]
    gemm_tc<64, 16><<<dim3(1, BS_TOK / 128), 256, GEMM_SMEM_64>>>(
        iv, Wv, bv, pV, BS_TOK, DK, D_MODEL);

    // Attention: 2 heads per CTA
    attn_tc<<<dim3(SEQ / 64, NHEADS / 2, BATCH), 256, ATTN_SMEM_TC>>>(
        pQ, pK, pV, pCtx);

    // Output projection: [4096,1024]
    gemm_tc<128, 32><<<dim3(D_MODEL / 128, BS_TOK / 128), 256, GEMM_SMEM_128>>>(
        pCtx, Wo, bo, out, BS_TOK, D_MODEL, D_MODEL);
}

// round 5
// speedup vs baseline: 2.9853x; 1.0344x over previous
#include <cuda_runtime.h>
#include <math.h>
#include <stdint.h>

#define D_MODEL 1024
#define NHEADS  16
#define DK      64
#define BATCH   2
#define SEQ     2048
#define BS_TOK  (BATCH * SEQ)   // 4096 tokens

// ---------------------------------------------------------------------------
// Scratch (device globals: no allocation allowed)
// ---------------------------------------------------------------------------
__device__ float g_Q[BS_TOK * D_MODEL];
__device__ float g_K[BS_TOK * DK];     // stored pre-rounded to tf32 bits
__device__ float g_V[BS_TOK * DK];     // stored pre-rounded to tf32 bits
__device__ float g_Ctx[BS_TOK * D_MODEL];

// ---------------------------------------------------------------------------
// tf32 + cp.async helpers
// ---------------------------------------------------------------------------
__device__ __forceinline__ unsigned f2tf(float x) {
    unsigned r;
    asm("cvt.rna.tf32.f32 %0, %1;" : "=r"(r) : "f"(x));
    return r;
}

__device__ __forceinline__ void cpa16(unsigned dst, const void* src) {
    asm volatile("cp.async.cg.shared.global [%0], [%1], 16;"
                 :: "r"(dst), "l"(src));
}
#define CP_COMMIT() asm volatile("cp.async.commit_group;" ::: "memory")
#define CP_WAIT0()  asm volatile("cp.async.wait_group 0;" ::: "memory")

// D = A(16x8,row) * B(8x8,col) + D, tf32 in, f32 accum
__device__ __forceinline__ void mma8(float* c, const unsigned* a,
                                     unsigned b0, unsigned b1) {
    asm volatile(
        "mma.sync.aligned.m16n8k8.row.col.f32.tf32.tf32.f32 "
        "{%0,%1,%2,%3}, {%4,%5,%6,%7}, {%8,%9}, {%0,%1,%2,%3};"
        : "+f"(c[0]), "+f"(c[1]), "+f"(c[2]), "+f"(c[3])
        : "r"(a[0]), "r"(a[1]), "r"(a[2]), "r"(a[3]), "r"(b0), "r"(b1));
}

// ---------------------------------------------------------------------------
// Tensor-core GEMM, double-buffered: C[M,N] = A[M,K] @ W[K,N] + bias
// RTF: round the output to tf32 bit pattern (for K/V feeding attention).
// ---------------------------------------------------------------------------
template<int BN, int WN, bool RTF>
__global__ __launch_bounds__(256)
void gemm_tc(const float* __restrict__ A, const float* __restrict__ W,
             const float* __restrict__ bias, float* __restrict__ C,
             int M, int N, int K)
{
    constexpr int BM = 128, BK = 32;
    constexpr int ASTR = BK + 4;       // 36
    constexpr int BSTR = BN + 8;       // 136 / 72
    constexpr int NF = WN / 8;
    constexpr int ABUF = BM * ASTR;
    constexpr int BBUF = BK * BSTR;
    constexpr int BF4 = (BK * BN / 4) / 256;
    extern __shared__ unsigned smg[];

    const int t = threadIdx.x, lane = t & 31, wp = t >> 5;
    const int wm0 = (wp >> 2) * 64, wn0 = (wp & 3) * WN;
    const int gid = lane >> 2, tig = lane & 3;
    const int m0 = blockIdx.y * BM, n0 = blockIdx.x * BN;

    float4 ra[4], rb[BF4];

    // ---- prologue: load + stage tile 0 ----
    #pragma unroll
    for (int i = 0; i < 4; ++i) {
        int idx = t + 256 * i;
        int r = idx >> 3, c4 = (idx & 7) * 4;
        ra[i] = *(const float4*)&A[(size_t)(m0 + r) * K + c4];
    }
    #pragma unroll
    for (int i = 0; i < BF4; ++i) {
        int idx = t + 256 * i;
        int r = idx / (BN / 4), c4 = (idx % (BN / 4)) * 4;
        rb[i] = *(const float4*)&W[(size_t)r * N + n0 + c4];
    }
    #pragma unroll
    for (int i = 0; i < 4; ++i) {
        int idx = t + 256 * i;
        int r = idx >> 3, c4 = (idx & 7) * 4;
        *(uint4*)&smg[r * ASTR + c4] =
            make_uint4(f2tf(ra[i].x), f2tf(ra[i].y), f2tf(ra[i].z), f2tf(ra[i].w));
    }
    #pragma unroll
    for (int i = 0; i < BF4; ++i) {
        int idx = t + 256 * i;
        int r = idx / (BN / 4), c4 = (idx % (BN / 4)) * 4;
        *(uint4*)&smg[2 * ABUF + r * BSTR + c4] =
            make_uint4(f2tf(rb[i].x), f2tf(rb[i].y), f2tf(rb[i].z), f2tf(rb[i].w));
    }
    __syncthreads();

    float acc[4][NF][4];
    #pragma unroll
    for (int mi = 0; mi < 4; ++mi)
        #pragma unroll
        for (int ni = 0; ni < NF; ++ni)
            #pragma unroll
            for (int x = 0; x < 4; ++x) acc[mi][ni][x] = 0.0f;

    int cur = 0;
    for (int k0 = 0; k0 < K; k0 += BK) {
        unsigned* As = smg + cur * ABUF;
        unsigned* Bs = smg + 2 * ABUF + cur * BBUF;
        const bool more = (k0 + BK) < K;

        if (more) {
            #pragma unroll
            for (int i = 0; i < 4; ++i) {
                int idx = t + 256 * i;
                int r = idx >> 3, c4 = (idx & 7) * 4;
                ra[i] = *(const float4*)&A[(size_t)(m0 + r) * K + k0 + BK + c4];
            }
            #pragma unroll
            for (int i = 0; i < BF4; ++i) {
                int idx = t + 256 * i;
                int r = idx / (BN / 4), c4 = (idx % (BN / 4)) * 4;
                rb[i] = *(const float4*)&W[(size_t)(k0 + BK + r) * N + n0 + c4];
            }
        }

        #pragma unroll
        for (int kk = 0; kk < 4; ++kk) {
            const int kc = kk * 8 + tig;
            unsigned a[4][4];
            #pragma unroll
            for (int mi = 0; mi < 4; ++mi) {
                int r = wm0 + mi * 16 + gid;
                a[mi][0] = As[r * ASTR + kc];
                a[mi][1] = As[(r + 8) * ASTR + kc];
                a[mi][2] = As[r * ASTR + kc + 4];
                a[mi][3] = As[(r + 8) * ASTR + kc + 4];
            }
            #pragma unroll
            for (int ni = 0; ni < NF; ++ni) {
                int n = wn0 + ni * 8 + gid;
                unsigned b0 = Bs[kc * BSTR + n];
                unsigned b1 = Bs[(kc + 4) * BSTR + n];
                #pragma unroll
                for (int mi = 0; mi < 4; ++mi) mma8(acc[mi][ni], a[mi], b0, b1);
            }
        }

        if (more) {
            unsigned* An = smg + (cur ^ 1) * ABUF;
            unsigned* Bn = smg + 2 * ABUF + (cur ^ 1) * BBUF;
            #pragma unroll
            for (int i = 0; i < 4; ++i) {
                int idx = t + 256 * i;
                int r = idx >> 3, c4 = (idx & 7) * 4;
                *(uint4*)&An[r * ASTR + c4] =
                    make_uint4(f2tf(ra[i].x), f2tf(ra[i].y),
                               f2tf(ra[i].z), f2tf(ra[i].w));
            }
            #pragma unroll
            for (int i = 0; i < BF4; ++i) {
                int idx = t + 256 * i;
                int r = idx / (BN / 4), c4 = (idx % (BN / 4)) * 4;
                *(uint4*)&Bn[r * BSTR + c4] =
                    make_uint4(f2tf(rb[i].x), f2tf(rb[i].y),
                               f2tf(rb[i].z), f2tf(rb[i].w));
            }
        }
        __syncthreads();
        cur ^= 1;
    }

    // ---- epilogue: bias + (optional tf32 round) + store ----
    #pragma unroll
    for (int mi = 0; mi < 4; ++mi) {
        int r = m0 + wm0 + mi * 16 + gid;
        #pragma unroll
        for (int ni = 0; ni < NF; ++ni) {
            int c = n0 + wn0 + ni * 8 + 2 * tig;
            float bb0 = bias[c], bb1 = bias[c + 1];
            float o0 = acc[mi][ni][0] + bb0, o1 = acc[mi][ni][1] + bb1;
            float o2 = acc[mi][ni][2] + bb0, o3 = acc[mi][ni][3] + bb1;
            if (RTF) {
                o0 = __uint_as_float(f2tf(o0));
                o1 = __uint_as_float(f2tf(o1));
                o2 = __uint_as_float(f2tf(o2));
                o3 = __uint_as_float(f2tf(o3));
            }
            *(float2*)&C[(size_t)r * N + c] = make_float2(o0, o1);
            *(float2*)&C[(size_t)(r + 8) * N + c] = make_float2(o2, o3);
        }
    }
}

#define GEMM_SMEM_128 ((2 * 128 * 36 + 2 * 32 * 136) * 4)   // 71680
#define GEMM_SMEM_64  ((2 * 128 * 36 + 2 * 32 * 72) * 4)    // 55296

// ---------------------------------------------------------------------------
// Tensor-core flash attention (MQA, causal), 2 heads per CTA,
// cp.async double-buffered K/V staging (K/V pre-rounded to tf32 bits by the
// projection GEMMs, so the DMA'd bytes feed MMA directly). One barrier/iter.
// smem: Ks[2][64][AS], Vs[2][64][AS], Ps[128][AS] (Q staging then P).
// ---------------------------------------------------------------------------
#define AS 68
#define ATTN_SMEM_TC ((4 * 64 + 128) * AS * 4)   // 104448 B

__global__ __launch_bounds__(256)
void attn_tc(const float* __restrict__ Q, const float* __restrict__ K,
             const float* __restrict__ V, float* __restrict__ Ctx)
{
    extern __shared__ unsigned smu[];
    const unsigned sb = (unsigned)__cvta_generic_to_shared(smu);
    unsigned* Ps = smu + 4 * 64 * AS;    // [128][AS]

    const int t = threadIdx.x, lane = t & 31, w = t >> 5;
    const int hw = w & 3;                // warp within head group
    const int gid = lane >> 2, tig = lane & 3;
    const int qt = (int)(gridDim.x - 1) - (int)blockIdx.x;  // long blocks first
    const int h = blockIdx.y * 2 + (w >> 2);
    const int b = blockIdx.z;

    // ---- prefetch K/V tile 0 via cp.async (buf 0) ----
    {
        #pragma unroll
        for (int ld = 0; ld < 4; ++ld) {
            int i = t + 256 * ld;
            int row = i >> 4, c4 = (i & 15) * 4;
            size_t g = ((size_t)(b * SEQ + row)) * DK + c4;
            unsigned so = (unsigned)(row * AS + c4) * 4u;
            cpa16(sb + so, K + g);
            cpa16(sb + (2 * 64 * AS) * 4u + so, V + g);
        }
        CP_COMMIT();
    }

    // ---- stage Q for both heads (pre-scaled), rows 0-63 = h0, 64-127 = h1 ----
    for (int i = t; i < 128 * 16; i += 256) {
        int row = i >> 4, c4 = (i & 15) * 4;
        int hh = blockIdx.y * 2 + (row >> 6);
        int qrow = row & 63;
        float4 v = *(const float4*)
            &Q[((size_t)(b * SEQ + qt * 64 + qrow)) * D_MODEL + hh * DK + c4];
        *(uint4*)&Ps[row * AS + c4] =
            make_uint4(f2tf(0.125f * v.x), f2tf(0.125f * v.y),
                       f2tf(0.125f * v.z), f2tf(0.125f * v.w));
    }
    CP_WAIT0();
    __syncthreads();

    unsigned Qa[8][4];
    {
        int r0 = 16 * w + gid;
        #pragma unroll
        for (int kf = 0; kf < 8; ++kf) {
            int kc = kf * 8 + tig;
            Qa[kf][0] = Ps[r0 * AS + kc];
            Qa[kf][1] = Ps[(r0 + 8) * AS + kc];
            Qa[kf][2] = Ps[r0 * AS + kc + 4];
            Qa[kf][3] = Ps[(r0 + 8) * AS + kc + 4];
        }
    }

    float m0 = -INFINITY, m1 = -INFINITY, l0 = 0.0f, l1 = 0.0f;
    float O[8][4];
    #pragma unroll
    for (int nf = 0; nf < 8; ++nf)
        #pragma unroll
        for (int x = 0; x < 4; ++x) O[nf][x] = 0.0f;

    int cur = 0;
    for (int j = 0; j <= qt; ++j) {
        unsigned* Ks = smu + cur * 64 * AS;
        unsigned* Vs = smu + (2 + cur) * 64 * AS;

        // ---- issue prefetch of tile j+1 into the other buffers ----
        if (j < qt) {
            const unsigned ko = (unsigned)((cur ^ 1) * 64 * AS) * 4u;
            const unsigned vo = (unsigned)((2 + (cur ^ 1)) * 64 * AS) * 4u;
            #pragma unroll
            for (int ld = 0; ld < 4; ++ld) {
                int i = t + 256 * ld;
                int row = i >> 4, c4 = (i & 15) * 4;
                size_t g = ((size_t)(b * SEQ + (j + 1) * 64 + row)) * DK + c4;
                unsigned so = (unsigned)(row * AS + c4) * 4u;
                cpa16(sb + ko + so, K + g);
                cpa16(sb + vo + so, V + g);
            }
            CP_COMMIT();
        }

        // ---- S = (Q/8) K^T : warp computes 16x64 ----
        float S[8][4];
        #pragma unroll
        for (int nf = 0; nf < 8; ++nf)
            #pragma unroll
            for (int x = 0; x < 4; ++x) S[nf][x] = 0.0f;
        #pragma unroll
        for (int kf = 0; kf < 8; ++kf) {
            const int kc = kf * 8 + tig;
            #pragma unroll
            for (int nf = 0; nf < 8; ++nf) {
                unsigned b0 = Ks[(nf * 8 + gid) * AS + kc];
                unsigned b1 = Ks[(nf * 8 + gid) * AS + kc + 4];
                mma8(S[nf], Qa[kf], b0, b1);
            }
        }

        // ---- causal mask on diagonal tile ----
        if (j == qt) {
            int qr = qt * 64 + 16 * hw + gid;
            #pragma unroll
            for (int nf = 0; nf < 8; ++nf) {
                int c0 = j * 64 + nf * 8 + 2 * tig;
                if (c0     > qr)     S[nf][0] = -INFINITY;
                if (c0 + 1 > qr)     S[nf][1] = -INFINITY;
                if (c0     > qr + 8) S[nf][2] = -INFINITY;
                if (c0 + 1 > qr + 8) S[nf][3] = -INFINITY;
            }
        }

        // ---- row max (rows gid / gid+8; reduce over quad lanes) ----
        float mx0 = -INFINITY, mx1 = -INFINITY;
        #pragma unroll
        for (int nf = 0; nf < 8; ++nf) {
            mx0 = fmaxf(mx0, fmaxf(S[nf][0], S[nf][1]));
            mx1 = fmaxf(mx1, fmaxf(S[nf][2], S[nf][3]));
        }
        mx0 = fmaxf(mx0, __shfl_xor_sync(0xffffffffu, mx0, 1));
        mx0 = fmaxf(mx0, __shfl_xor_sync(0xffffffffu, mx0, 2));
        mx1 = fmaxf(mx1, __shfl_xor_sync(0xffffffffu, mx1, 1));
        mx1 = fmaxf(mx1, __shfl_xor_sync(0xffffffffu, mx1, 2));

        float mn0 = fmaxf(m0, mx0), mn1 = fmaxf(m1, mx1);
        float cr0 = __expf(m0 - mn0), cr1 = __expf(m1 - mn1);
        m0 = mn0; m1 = mn1;

        float rs0 = 0.0f, rs1 = 0.0f;
        #pragma unroll
        for (int nf = 0; nf < 8; ++nf) {
            S[nf][0] = __expf(S[nf][0] - mn0);
            S[nf][1] = __expf(S[nf][1] - mn0);
            S[nf][2] = __expf(S[nf][2] - mn1);
            S[nf][3] = __expf(S[nf][3] - mn1);
            rs0 += S[nf][0] + S[nf][1];
            rs1 += S[nf][2] + S[nf][3];
        }
        rs0 += __shfl_xor_sync(0xffffffffu, rs0, 1);
        rs0 += __shfl_xor_sync(0xffffffffu, rs0, 2);
        rs1 += __shfl_xor_sync(0xffffffffu, rs1, 1);
        rs1 += __shfl_xor_sync(0xffffffffu, rs1, 2);
        l0 = l0 * cr0 + rs0;
        l1 = l1 * cr1 + rs1;
        #pragma unroll
        for (int nf = 0; nf < 8; ++nf) {
            O[nf][0] *= cr0; O[nf][1] *= cr0;
            O[nf][2] *= cr1; O[nf][3] *= cr1;
        }

        // ---- P -> smem (warp-private rows), then O += P V ----
        const int pr = 16 * w + gid;
        __syncwarp();   // lanes of this warp done reading Ps rows (Qa/prev PV)
        #pragma unroll
        for (int nf = 0; nf < 8; ++nf) {
            int pc = nf * 8 + 2 * tig;
            *(uint2*)&Ps[pr * AS + pc] =
                make_uint2(f2tf(S[nf][0]), f2tf(S[nf][1]));
            *(uint2*)&Ps[(pr + 8) * AS + pc] =
                make_uint2(f2tf(S[nf][2]), f2tf(S[nf][3]));
        }
        __syncwarp();
        #pragma unroll
        for (int kf = 0; kf < 8; ++kf) {
            const int kc = kf * 8 + tig;
            unsigned pa[4];
            pa[0] = Ps[pr * AS + kc];
            pa[1] = Ps[(pr + 8) * AS + kc];
            pa[2] = Ps[pr * AS + kc + 4];
            pa[3] = Ps[(pr + 8) * AS + kc + 4];
            #pragma unroll
            for (int nf = 0; nf < 8; ++nf) {
                unsigned b0 = Vs[kc * AS + nf * 8 + gid];
                unsigned b1 = Vs[(kc + 4) * AS + nf * 8 + gid];
                mma8(O[nf], pa, b0, b1);
            }
        }

        CP_WAIT0();        // prefetched tile landed
        __syncthreads();   // all warps done with cur buffers
        cur ^= 1;
    }

    // ---- normalize + write context ----
    float inv0 = 1.0f / l0, inv1 = 1.0f / l1;
    int r0 = qt * 64 + 16 * hw + gid;
    #pragma unroll
    for (int nf = 0; nf < 8; ++nf) {
        int c = h * DK + nf * 8 + 2 * tig;
        *(float2*)&Ctx[((size_t)(b * SEQ + r0)) * D_MODEL + c] =
            make_float2(O[nf][0] * inv0, O[nf][1] * inv0);
        *(float2*)&Ctx[((size_t)(b * SEQ + r0 + 8)) * D_MODEL + c] =
            make_float2(O[nf][2] * inv1, O[nf][3] * inv1);
    }
}

// ---------------------------------------------------------------------------
// launch
// ---------------------------------------------------------------------------
extern "C" void kernel_launch(void* const* d_in, const int* in_sizes, int n_in,
                              void* d_out, int out_size)
{
    const float* iq = (const float*)d_in[0];
    const float* ik = (const float*)d_in[1];
    const float* iv = (const float*)d_in[2];
    const float* Wq = (const float*)d_in[3];
    const float* bq = (const float*)d_in[4];
    const float* Wk = (const float*)d_in[5];
    const float* bk = (const float*)d_in[6];
    const float* Wv = (const float*)d_in[7];
    const float* bv = (const float*)d_in[8];
    const float* Wo = (const float*)d_in[9];
    const float* bo = (const float*)d_in[10];
    float* out = (float*)d_out;

    float *pQ, *pK, *pV, *pCtx;
    cudaGetSymbolAddress((void**)&pQ,   g_Q);
    cudaGetSymbolAddress((void**)&pK,   g_K);
    cudaGetSymbolAddress((void**)&pV,   g_V);
    cudaGetSymbolAddress((void**)&pCtx, g_Ctx);

    cudaFuncSetAttribute((const void*)gemm_tc<128, 32, false>,
                         cudaFuncAttributeMaxDynamicSharedMemorySize,
                         GEMM_SMEM_128);
    cudaFuncSetAttribute((const void*)gemm_tc<64, 16, true>,
                         cudaFuncAttributeMaxDynamicSharedMemorySize,
                         GEMM_SMEM_64);
    cudaFuncSetAttribute((const void*)attn_tc,
                         cudaFuncAttributeMaxDynamicSharedMemorySize,
                         ATTN_SMEM_TC);

    // Q projection: [4096,1024] = [4096,1024] @ [1024,1024]
    gemm_tc<128, 32, false>
        <<<dim3(D_MODEL / 128, BS_TOK / 128), 256, GEMM_SMEM_128>>>(
        iq, Wq, bq, pQ, BS_TOK, D_MODEL, D_MODEL);
    // K projection: [4096,64], output rounded to tf32 bits
    gemm_tc<64, 16, true><<<dim3(1, BS_TOK / 128), 256, GEMM_SMEM_64>>>(
        ik, Wk, bk, pK, BS_TOK, DK, D_MODEL);
    // V projection: [4096,64], output rounded to tf32 bits
    gemm_tc<64, 16, true><<<dim3(1, BS_TOK / 128), 256, GEMM_SMEM_64>>>(
        iv, Wv, bv, pV, BS_TOK, DK, D_MODEL);

    // Attention: 2 heads per CTA, cp.async pipelined K/V
    attn_tc<<<dim3(SEQ / 64, NHEADS / 2, BATCH), 256, ATTN_SMEM_TC>>>(
        pQ, pK, pV, pCtx);

    // Output projection: [4096,1024]
    gemm_tc<128, 32, false>
        <<<dim3(D_MODEL / 128, BS_TOK / 128), 256, GEMM_SMEM_128>>>(
        pCtx, Wo, bo, out, BS_TOK, D_MODEL, D_MODEL);
}

// round 6
// speedup vs baseline: 3.3603x; 1.1256x over previous
#include <cuda_runtime.h>
#include <math.h>
#include <stdint.h>

#define D_MODEL 1024
#define NHEADS  16
#define DK      64
#define BATCH   2
#define SEQ     2048
#define BS_TOK  (BATCH * SEQ)   // 4096 tokens

// ---------------------------------------------------------------------------
// Scratch (device globals: no allocation allowed)
// ---------------------------------------------------------------------------
__device__ float g_Q[BS_TOK * D_MODEL];
__device__ float g_K[BS_TOK * DK];     // tf32-rounded, [b*S+s][dk]
__device__ float g_Vt[BS_TOK * DK];    // tf32-rounded, TRANSPOSED [b][dv][s]
__device__ float g_Ctx[BS_TOK * D_MODEL];

// ---------------------------------------------------------------------------
// tf32 / cp.async / ldmatrix helpers
// ---------------------------------------------------------------------------
__device__ __forceinline__ unsigned f2tf(float x) {
    unsigned r;
    asm("cvt.rna.tf32.f32 %0, %1;" : "=r"(r) : "f"(x));
    return r;
}

__device__ __forceinline__ void cpa16(unsigned dst, const void* src) {
    asm volatile("cp.async.cg.shared.global [%0], [%1], 16;"
                 :: "r"(dst), "l"(src));
}
#define CP_COMMIT() asm volatile("cp.async.commit_group;" ::: "memory")
#define CP_WAIT0()  asm volatile("cp.async.wait_group 0;" ::: "memory")

// x4 ldmatrix: four 8x8 b16 (= 8x4 tf32) tiles; lane i supplies row (i&7) of
// matrix (i>>3).
__device__ __forceinline__ void ldsm4(unsigned* r, unsigned addr) {
    asm volatile("ldmatrix.sync.aligned.m8n8.x4.shared.b16 {%0,%1,%2,%3}, [%4];"
                 : "=r"(r[0]), "=r"(r[1]), "=r"(r[2]), "=r"(r[3]) : "r"(addr));
}

// D = A(16x8,row) * B(8x8,col) + D, tf32 in, f32 accum
__device__ __forceinline__ void mma8(float* c, const unsigned* a,
                                     unsigned b0, unsigned b1) {
    asm volatile(
        "mma.sync.aligned.m16n8k8.row.col.f32.tf32.tf32.f32 "
        "{%0,%1,%2,%3}, {%4,%5,%6,%7}, {%8,%9}, {%0,%1,%2,%3};"
        : "+f"(c[0]), "+f"(c[1]), "+f"(c[2]), "+f"(c[3])
        : "r"(a[0]), "r"(a[1]), "r"(a[2]), "r"(a[3]), "r"(b0), "r"(b1));
}

// ---------------------------------------------------------------------------
// Tensor-core GEMM, double-buffered. RTF: round output to tf32 bits.
// TRV: write output transposed as Vt[b][dv][s] (for V projection).
// A-fragments fetched with ldmatrix.
// ---------------------------------------------------------------------------
template<int BN, int WN, bool RTF, bool TRV>
__global__ __launch_bounds__(256)
void gemm_tc(const float* __restrict__ A, const float* __restrict__ W,
             const float* __restrict__ bias, float* __restrict__ C,
             int M, int N, int K)
{
    constexpr int BM = 128, BK = 32;
    constexpr int ASTR = BK + 4;       // 36
    constexpr int BSTR = BN + 8;       // 136 / 72
    constexpr int NF = WN / 8;
    constexpr int ABUF = BM * ASTR;
    constexpr int BBUF = BK * BSTR;
    constexpr int BF4 = (BK * BN / 4) / 256;
    extern __shared__ unsigned smg[];
    const unsigned sb = (unsigned)__cvta_generic_to_shared(smg);

    const int t = threadIdx.x, lane = t & 31, wp = t >> 5;
    const int wm0 = (wp >> 2) * 64, wn0 = (wp & 3) * WN;
    const int gid = lane >> 2, tig = lane & 3;
    const int m0 = blockIdx.y * BM, n0 = blockIdx.x * BN;

    // A-pattern ldmatrix lane offset (bytes, within a 16x8 tf32 tile):
    const int m4 = lane >> 3, j8 = lane & 7;
    const unsigned a_loff = (unsigned)((((m4 & 1) * 8 + j8) * ASTR +
                                        (m4 >> 1) * 4) * 4);

    float4 ra[4], rb[BF4];

    // ---- prologue: load + stage tile 0 ----
    #pragma unroll
    for (int i = 0; i < 4; ++i) {
        int idx = t + 256 * i;
        int r = idx >> 3, c4 = (idx & 7) * 4;
        ra[i] = *(const float4*)&A[(size_t)(m0 + r) * K + c4];
    }
    #pragma unroll
    for (int i = 0; i < BF4; ++i) {
        int idx = t + 256 * i;
        int r = idx / (BN / 4), c4 = (idx % (BN / 4)) * 4;
        rb[i] = *(const float4*)&W[(size_t)r * N + n0 + c4];
    }
    #pragma unroll
    for (int i = 0; i < 4; ++i) {
        int idx = t + 256 * i;
        int r = idx >> 3, c4 = (idx & 7) * 4;
        *(uint4*)&smg[r * ASTR + c4] =
            make_uint4(f2tf(ra[i].x), f2tf(ra[i].y), f2tf(ra[i].z), f2tf(ra[i].w));
    }
    #pragma unroll
    for (int i = 0; i < BF4; ++i) {
        int idx = t + 256 * i;
        int r = idx / (BN / 4), c4 = (idx % (BN / 4)) * 4;
        *(uint4*)&smg[2 * ABUF + r * BSTR + c4] =
            make_uint4(f2tf(rb[i].x), f2tf(rb[i].y), f2tf(rb[i].z), f2tf(rb[i].w));
    }
    __syncthreads();

    float acc[4][NF][4];
    #pragma unroll
    for (int mi = 0; mi < 4; ++mi)
        #pragma unroll
        for (int ni = 0; ni < NF; ++ni)
            #pragma unroll
            for (int x = 0; x < 4; ++x) acc[mi][ni][x] = 0.0f;

    int cur = 0;
    for (int k0 = 0; k0 < K; k0 += BK) {
        unsigned* Bs = smg + 2 * ABUF + cur * BBUF;
        const unsigned as_addr = sb + (unsigned)(cur * ABUF * 4) +
                                 (unsigned)(wm0 * ASTR * 4) + a_loff;
        const bool more = (k0 + BK) < K;

        if (more) {
            #pragma unroll
            for (int i = 0; i < 4; ++i) {
                int idx = t + 256 * i;
                int r = idx >> 3, c4 = (idx & 7) * 4;
                ra[i] = *(const float4*)&A[(size_t)(m0 + r) * K + k0 + BK + c4];
            }
            #pragma unroll
            for (int i = 0; i < BF4; ++i) {
                int idx = t + 256 * i;
                int r = idx / (BN / 4), c4 = (idx % (BN / 4)) * 4;
                rb[i] = *(const float4*)&W[(size_t)(k0 + BK + r) * N + n0 + c4];
            }
        }

        #pragma unroll
        for (int kk = 0; kk < 4; ++kk) {
            const int kc = kk * 8 + tig;
            unsigned a[4][4];
            #pragma unroll
            for (int mi = 0; mi < 4; ++mi)
                ldsm4(a[mi], as_addr + (unsigned)(mi * 16 * ASTR * 4 + kk * 32));
            #pragma unroll
            for (int ni = 0; ni < NF; ++ni) {
                int n = wn0 + ni * 8 + gid;
                unsigned b0 = Bs[kc * BSTR + n];
                unsigned b1 = Bs[(kc + 4) * BSTR + n];
                #pragma unroll
                for (int mi = 0; mi < 4; ++mi) mma8(acc[mi][ni], a[mi], b0, b1);
            }
        }

        if (more) {
            unsigned* An = smg + (cur ^ 1) * ABUF;
            unsigned* Bn = smg + 2 * ABUF + (cur ^ 1) * BBUF;
            #pragma unroll
            for (int i = 0; i < 4; ++i) {
                int idx = t + 256 * i;
                int r = idx >> 3, c4 = (idx & 7) * 4;
                *(uint4*)&An[r * ASTR + c4] =
                    make_uint4(f2tf(ra[i].x), f2tf(ra[i].y),
                               f2tf(ra[i].z), f2tf(ra[i].w));
            }
            #pragma unroll
            for (int i = 0; i < BF4; ++i) {
                int idx = t + 256 * i;
                int r = idx / (BN / 4), c4 = (idx % (BN / 4)) * 4;
                *(uint4*)&Bn[r * BSTR + c4] =
                    make_uint4(f2tf(rb[i].x), f2tf(rb[i].y),
                               f2tf(rb[i].z), f2tf(rb[i].w));
            }
        }
        __syncthreads();
        cur ^= 1;
    }

    // ---- epilogue ----
    #pragma unroll
    for (int mi = 0; mi < 4; ++mi) {
        int r = m0 + wm0 + mi * 16 + gid;
        #pragma unroll
        for (int ni = 0; ni < NF; ++ni) {
            int c = n0 + wn0 + ni * 8 + 2 * tig;
            float bb0 = bias[c], bb1 = bias[c + 1];
            float o0 = acc[mi][ni][0] + bb0, o1 = acc[mi][ni][1] + bb1;
            float o2 = acc[mi][ni][2] + bb0, o3 = acc[mi][ni][3] + bb1;
            if (RTF) {
                o0 = __uint_as_float(f2tf(o0));
                o1 = __uint_as_float(f2tf(o1));
                o2 = __uint_as_float(f2tf(o2));
                o3 = __uint_as_float(f2tf(o3));
            }
            if (TRV) {
                // write transposed: Vt[b][dv][s], s = r mod SEQ
                int bb_ = r >> 11, ss = r & (SEQ - 1);
                C[((size_t)(bb_ * DK + c))     * SEQ + ss]     = o0;
                C[((size_t)(bb_ * DK + c + 1)) * SEQ + ss]     = o1;
                C[((size_t)(bb_ * DK + c))     * SEQ + ss + 8] = o2;
                C[((size_t)(bb_ * DK + c + 1)) * SEQ + ss + 8] = o3;
            } else {
                *(float2*)&C[(size_t)r * N + c] = make_float2(o0, o1);
                *(float2*)&C[(size_t)(r + 8) * N + c] = make_float2(o2, o3);
            }
        }
    }
}

#define GEMM_SMEM_128 ((2 * 128 * 36 + 2 * 32 * 136) * 4)   // 71680
#define GEMM_SMEM_64  ((2 * 128 * 36 + 2 * 32 * 72) * 4)    // 55296

// ---------------------------------------------------------------------------
// Tensor-core flash attention (MQA, causal), 2 heads per CTA, cp.async
// double-buffered K/Vt staging, all fragments via ldmatrix.
// smem: Ks[2][64][AS] ([kpos][d]), Vts[2][64][AS] ([dv][kpos]),
//       Ps[128][AS] (Q staging then P).
// ---------------------------------------------------------------------------
#define AS 68
#define ATTN_SMEM_TC ((4 * 64 + 128) * AS * 4)   // 104448 B

__global__ __launch_bounds__(256)
void attn_tc(const float* __restrict__ Q, const float* __restrict__ K,
             const float* __restrict__ Vt, float* __restrict__ Ctx)
{
    extern __shared__ unsigned smu[];
    const unsigned sb = (unsigned)__cvta_generic_to_shared(smu);
    unsigned* Ps = smu + 4 * 64 * AS;    // [128][AS]
    const unsigned ps_base = sb + (unsigned)(4 * 64 * AS * 4);

    const int t = threadIdx.x, lane = t & 31, w = t >> 5;
    const int hw = w & 3;
    const int gid = lane >> 2, tig = lane & 3;
    const int qt = (int)(gridDim.x - 1) - (int)blockIdx.x;  // long blocks first
    const int h = blockIdx.y * 2 + (w >> 2);
    const int b = blockIdx.z;

    // ldmatrix lane offsets (bytes)
    const int m4 = lane >> 3, j8 = lane & 7;
    const unsigned a_loff = (unsigned)((((m4 & 1) * 8 + j8) * AS +
                                        (m4 >> 1) * 4) * 4);     // A pattern
    const unsigned b_loff = (unsigned)((((m4 >> 1) * 8 + j8) * AS +
                                        (m4 & 1) * 4) * 4);     // B pair pattern

    // ---- prefetch K/Vt tile 0 via cp.async (buf 0) ----
    {
        #pragma unroll
        for (int ld = 0; ld < 4; ++ld) {
            int i = t + 256 * ld;
            int row = i >> 4, c4 = (i & 15) * 4;
            unsigned so = (unsigned)(row * AS + c4) * 4u;
            cpa16(sb + so, K + ((size_t)(b * SEQ + row)) * DK + c4);
            cpa16(sb + (2 * 64 * AS) * 4u + so,
                  Vt + ((size_t)(b * DK + row)) * SEQ + c4);
        }
        CP_COMMIT();
    }

    // ---- stage Q for both heads (pre-scaled), rows 0-63 = h0, 64-127 = h1 ----
    for (int i = t; i < 128 * 16; i += 256) {
        int row = i >> 4, c4 = (i & 15) * 4;
        int hh = blockIdx.y * 2 + (row >> 6);
        int qrow = row & 63;
        float4 v = *(const float4*)
            &Q[((size_t)(b * SEQ + qt * 64 + qrow)) * D_MODEL + hh * DK + c4];
        *(uint4*)&Ps[row * AS + c4] =
            make_uint4(f2tf(0.125f * v.x), f2tf(0.125f * v.y),
                       f2tf(0.125f * v.z), f2tf(0.125f * v.w));
    }
    CP_WAIT0();
    __syncthreads();

    const unsigned ps_warp = ps_base + (unsigned)(16 * w * AS * 4);
    unsigned Qa[8][4];
    #pragma unroll
    for (int kf = 0; kf < 8; ++kf)
        ldsm4(Qa[kf], ps_warp + a_loff + kf * 32);

    float m0 = -INFINITY, m1 = -INFINITY, l0 = 0.0f, l1 = 0.0f;
    float O[8][4];
    #pragma unroll
    for (int nf = 0; nf < 8; ++nf)
        #pragma unroll
        for (int x = 0; x < 4; ++x) O[nf][x] = 0.0f;

    int cur = 0;
    for (int j = 0; j <= qt; ++j) {
        const unsigned ks_base = sb + (unsigned)(cur * 64 * AS * 4);
        const unsigned vt_base = sb + (unsigned)((2 + cur) * 64 * AS * 4);

        // ---- issue prefetch of tile j+1 into the other buffers ----
        if (j < qt) {
            const unsigned ko = (unsigned)((cur ^ 1) * 64 * AS) * 4u;
            const unsigned vo = (unsigned)((2 + (cur ^ 1)) * 64 * AS) * 4u;
            #pragma unroll
            for (int ld = 0; ld < 4; ++ld) {
                int i = t + 256 * ld;
                int row = i >> 4, c4 = (i & 15) * 4;
                unsigned so = (unsigned)(row * AS + c4) * 4u;
                cpa16(sb + ko + so,
                      K + ((size_t)(b * SEQ + (j + 1) * 64 + row)) * DK + c4);
                cpa16(sb + vo + so,
                      Vt + ((size_t)(b * DK + row)) * SEQ + (j + 1) * 64 + c4);
            }
            CP_COMMIT();
        }

        // ---- S = (Q/8) K^T : warp computes 16x64, B-frags via ldmatrix ----
        float S[8][4];
        #pragma unroll
        for (int nf = 0; nf < 8; ++nf)
            #pragma unroll
            for (int x = 0; x < 4; ++x) S[nf][x] = 0.0f;
        #pragma unroll
        for (int kf = 0; kf < 8; ++kf) {
            #pragma unroll
            for (int nfp = 0; nfp < 4; ++nfp) {
                unsigned bb[4];
                ldsm4(bb, ks_base + (unsigned)(nfp * 16 * AS * 4) + b_loff
                          + kf * 32);
                mma8(S[2 * nfp],     Qa[kf], bb[0], bb[1]);
                mma8(S[2 * nfp + 1], Qa[kf], bb[2], bb[3]);
            }
        }

        // ---- causal mask on diagonal tile ----
        if (j == qt) {
            int qr = qt * 64 + 16 * hw + gid;
            #pragma unroll
            for (int nf = 0; nf < 8; ++nf) {
                int c0 = j * 64 + nf * 8 + 2 * tig;
                if (c0     > qr)     S[nf][0] = -INFINITY;
                if (c0 + 1 > qr)     S[nf][1] = -INFINITY;
                if (c0     > qr + 8) S[nf][2] = -INFINITY;
                if (c0 + 1 > qr + 8) S[nf][3] = -INFINITY;
            }
        }

        // ---- row max + online softmax ----
        float mx0 = -INFINITY, mx1 = -INFINITY;
        #pragma unroll
        for (int nf = 0; nf < 8; ++nf) {
            mx0 = fmaxf(mx0, fmaxf(S[nf][0], S[nf][1]));
            mx1 = fmaxf(mx1, fmaxf(S[nf][2], S[nf][3]));
        }
        mx0 = fmaxf(mx0, __shfl_xor_sync(0xffffffffu, mx0, 1));
        mx0 = fmaxf(mx0, __shfl_xor_sync(0xffffffffu, mx0, 2));
        mx1 = fmaxf(mx1, __shfl_xor_sync(0xffffffffu, mx1, 1));
        mx1 = fmaxf(mx1, __shfl_xor_sync(0xffffffffu, mx1, 2));

        float mn0 = fmaxf(m0, mx0), mn1 = fmaxf(m1, mx1);
        float cr0 = __expf(m0 - mn0), cr1 = __expf(m1 - mn1);
        m0 = mn0; m1 = mn1;

        float rs0 = 0.0f, rs1 = 0.0f;
        #pragma unroll
        for (int nf = 0; nf < 8; ++nf) {
            S[nf][0] = __expf(S[nf][0] - mn0);
            S[nf][1] = __expf(S[nf][1] - mn0);
            S[nf][2] = __expf(S[nf][2] - mn1);
            S[nf][3] = __expf(S[nf][3] - mn1);
            rs0 += S[nf][0] + S[nf][1];
            rs1 += S[nf][2] + S[nf][3];
        }
        rs0 += __shfl_xor_sync(0xffffffffu, rs0, 1);
        rs0 += __shfl_xor_sync(0xffffffffu, rs0, 2);
        rs1 += __shfl_xor_sync(0xffffffffu, rs1, 1);
        rs1 += __shfl_xor_sync(0xffffffffu, rs1, 2);
        l0 = l0 * cr0 + rs0;
        l1 = l1 * cr1 + rs1;
        #pragma unroll
        for (int nf = 0; nf < 8; ++nf) {
            O[nf][0] *= cr0; O[nf][1] *= cr0;
            O[nf][2] *= cr1; O[nf][3] *= cr1;
        }

        // ---- P -> smem (warp-private rows), then O += P V ----
        const int pr = 16 * w + gid;
        __syncwarp();
        #pragma unroll
        for (int nf = 0; nf < 8; ++nf) {
            int pc = nf * 8 + 2 * tig;
            *(uint2*)&Ps[pr * AS + pc] =
                make_uint2(f2tf(S[nf][0]), f2tf(S[nf][1]));
            *(uint2*)&Ps[(pr + 8) * AS + pc] =
                make_uint2(f2tf(S[nf][2]), f2tf(S[nf][3]));
        }
        __syncwarp();
        #pragma unroll
        for (int kf = 0; kf < 8; ++kf) {
            unsigned pa[4];
            ldsm4(pa, ps_warp + a_loff + kf * 32);
            #pragma unroll
            for (int nfp = 0; nfp < 4; ++nfp) {
                unsigned vb[4];
                ldsm4(vb, vt_base + (unsigned)(nfp * 16 * AS * 4) + b_loff
                          + kf * 32);
                mma8(O[2 * nfp],     pa, vb[0], vb[1]);
                mma8(O[2 * nfp + 1], pa, vb[2], vb[3]);
            }
        }

        CP_WAIT0();
        __syncthreads();
        cur ^= 1;
    }

    // ---- normalize + write context ----
    float inv0 = 1.0f / l0, inv1 = 1.0f / l1;
    int r0 = qt * 64 + 16 * hw + gid;
    #pragma unroll
    for (int nf = 0; nf < 8; ++nf) {
        int c = h * DK + nf * 8 + 2 * tig;
        *(float2*)&Ctx[((size_t)(b * SEQ + r0)) * D_MODEL + c] =
            make_float2(O[nf][0] * inv0, O[nf][1] * inv0);
        *(float2*)&Ctx[((size_t)(b * SEQ + r0 + 8)) * D_MODEL + c] =
            make_float2(O[nf][2] * inv1, O[nf][3] * inv1);
    }
}

// ---------------------------------------------------------------------------
// launch
// ---------------------------------------------------------------------------
extern "C" void kernel_launch(void* const* d_in, const int* in_sizes, int n_in,
                              void* d_out, int out_size)
{
    const float* iq = (const float*)d_in[0];
    const float* ik = (const float*)d_in[1];
    const float* iv = (const float*)d_in[2];
    const float* Wq = (const float*)d_in[3];
    const float* bq = (const float*)d_in[4];
    const float* Wk = (const float*)d_in[5];
    const float* bk = (const float*)d_in[6];
    const float* Wv = (const float*)d_in[7];
    const float* bv = (const float*)d_in[8];
    const float* Wo = (const float*)d_in[9];
    const float* bo = (const float*)d_in[10];
    float* out = (float*)d_out;

    float *pQ, *pK, *pVt, *pCtx;
    cudaGetSymbolAddress((void**)&pQ,   g_Q);
    cudaGetSymbolAddress((void**)&pK,   g_K);
    cudaGetSymbolAddress((void**)&pVt,  g_Vt);
    cudaGetSymbolAddress((void**)&pCtx, g_Ctx);

    cudaFuncSetAttribute((const void*)gemm_tc<128, 32, false, false>,
                         cudaFuncAttributeMaxDynamicSharedMemorySize,
                         GEMM_SMEM_128);
    cudaFuncSetAttribute((const void*)gemm_tc<64, 16, true, false>,
                         cudaFuncAttributeMaxDynamicSharedMemorySize,
                         GEMM_SMEM_64);
    cudaFuncSetAttribute((const void*)gemm_tc<64, 16, true, true>,
                         cudaFuncAttributeMaxDynamicSharedMemorySize,
                         GEMM_SMEM_64);
    cudaFuncSetAttribute((const void*)attn_tc,
                         cudaFuncAttributeMaxDynamicSharedMemorySize,
                         ATTN_SMEM_TC);

    // Q projection
    gemm_tc<128, 32, false, false>
        <<<dim3(D_MODEL / 128, BS_TOK / 128), 256, GEMM_SMEM_128>>>(
        iq, Wq, bq, pQ, BS_TOK, D_MODEL, D_MODEL);
    // K projection (tf32-rounded, row-major)
    gemm_tc<64, 16, true, false><<<dim3(1, BS_TOK / 128), 256, GEMM_SMEM_64>>>(
        ik, Wk, bk, pK, BS_TOK, DK, D_MODEL);
    // V projection (tf32-rounded, transposed -> Vt[b][dv][s])
    gemm_tc<64, 16, true, true><<<dim3(1, BS_TOK / 128), 256, GEMM_SMEM_64>>>(
        iv, Wv, bv, pVt, BS_TOK, DK, D_MODEL);

    // Attention
    attn_tc<<<dim3(SEQ / 64, NHEADS / 2, BATCH), 256, ATTN_SMEM_TC>>>(
        pQ, pK, pVt, pCtx);

    // Output projection
    gemm_tc<128, 32, false, false>
        <<<dim3(D_MODEL / 128, BS_TOK / 128), 256, GEMM_SMEM_128>>>(
        pCtx, Wo, bo, out, BS_TOK, D_MODEL, D_MODEL);
}

// round 7
// speedup vs baseline: 3.7475x; 1.1152x over previous
#include <cuda_runtime.h>
#include <math.h>
#include <stdint.h>

#define D_MODEL 1024
#define NHEADS  16
#define DK      64
#define BATCH   2
#define SEQ     2048
#define BS_TOK  (BATCH * SEQ)   // 4096 tokens

// ---------------------------------------------------------------------------
// Scratch (device globals: no allocation allowed)
// ---------------------------------------------------------------------------
__device__ float g_Q[BS_TOK * D_MODEL];
__device__ float g_K[BS_TOK * DK];     // tf32-rounded, [b*S+s][dk]
__device__ float g_Vt[BS_TOK * DK];    // tf32-rounded, TRANSPOSED [b][dv][s]
__device__ float g_Ctx[BS_TOK * D_MODEL];

// ---------------------------------------------------------------------------
// tf32 / cp.async / ldmatrix helpers
// ---------------------------------------------------------------------------
__device__ __forceinline__ unsigned f2tf(float x) {
    unsigned r;
    asm("cvt.rna.tf32.f32 %0, %1;" : "=r"(r) : "f"(x));
    return r;
}

__device__ __forceinline__ void cpa16(unsigned dst, const void* src) {
    asm volatile("cp.async.cg.shared.global [%0], [%1], 16;"
                 :: "r"(dst), "l"(src));
}
#define CP_COMMIT() asm volatile("cp.async.commit_group;" ::: "memory")
#define CP_WAIT0()  asm volatile("cp.async.wait_group 0;" ::: "memory")

__device__ __forceinline__ void ldsm4(unsigned* r, unsigned addr) {
    asm volatile("ldmatrix.sync.aligned.m8n8.x4.shared.b16 {%0,%1,%2,%3}, [%4];"
                 : "=r"(r[0]), "=r"(r[1]), "=r"(r[2]), "=r"(r[3]) : "r"(addr));
}

// D = A(16x8,row) * B(8x8,col) + D, tf32 in, f32 accum
__device__ __forceinline__ void mma8(float* c, const unsigned* a,
                                     unsigned b0, unsigned b1) {
    asm volatile(
        "mma.sync.aligned.m16n8k8.row.col.f32.tf32.tf32.f32 "
        "{%0,%1,%2,%3}, {%4,%5,%6,%7}, {%8,%9}, {%0,%1,%2,%3};"
        : "+f"(c[0]), "+f"(c[1]), "+f"(c[2]), "+f"(c[3])
        : "r"(a[0]), "r"(a[1]), "r"(a[2]), "r"(a[3]), "r"(b0), "r"(b1));
}

// ---------------------------------------------------------------------------
// Tensor-core GEMM core (double-buffered), shared by all projections.
// rtf: round output to tf32 bits. trv: write transposed Vt[b][dv][s].
// ---------------------------------------------------------------------------
template<int BN, int WN>
__device__ __forceinline__
void gemm_body(const float* __restrict__ A, const float* __restrict__ W,
               const float* __restrict__ bias, float* __restrict__ C,
               int M, int N, int K, int m0, int n0, bool rtf, bool trv)
{
    constexpr int BM = 128, BK = 32;
    constexpr int ASTR = BK + 4;       // 36
    constexpr int BSTR = BN + 8;
    constexpr int NF = WN / 8;
    constexpr int ABUF = BM * ASTR;
    constexpr int BBUF = BK * BSTR;
    constexpr int BF4 = (BK * BN / 4) / 256;
    extern __shared__ unsigned smg[];
    const unsigned sb = (unsigned)__cvta_generic_to_shared(smg);

    const int t = threadIdx.x, lane = t & 31, wp = t >> 5;
    const int wm0 = (wp >> 2) * 64, wn0 = (wp & 3) * WN;
    const int gid = lane >> 2, tig = lane & 3;

    const int m4 = lane >> 3, j8 = lane & 7;
    const unsigned a_loff = (unsigned)((((m4 & 1) * 8 + j8) * ASTR +
                                        (m4 >> 1) * 4) * 4);

    float4 ra[4], rb[BF4];

    #pragma unroll
    for (int i = 0; i < 4; ++i) {
        int idx = t + 256 * i;
        int r = idx >> 3, c4 = (idx & 7) * 4;
        ra[i] = *(const float4*)&A[(size_t)(m0 + r) * K + c4];
    }
    #pragma unroll
    for (int i = 0; i < BF4; ++i) {
        int idx = t + 256 * i;
        int r = idx / (BN / 4), c4 = (idx % (BN / 4)) * 4;
        rb[i] = *(const float4*)&W[(size_t)r * N + n0 + c4];
    }
    #pragma unroll
    for (int i = 0; i < 4; ++i) {
        int idx = t + 256 * i;
        int r = idx >> 3, c4 = (idx & 7) * 4;
        *(uint4*)&smg[r * ASTR + c4] =
            make_uint4(f2tf(ra[i].x), f2tf(ra[i].y), f2tf(ra[i].z), f2tf(ra[i].w));
    }
    #pragma unroll
    for (int i = 0; i < BF4; ++i) {
        int idx = t + 256 * i;
        int r = idx / (BN / 4), c4 = (idx % (BN / 4)) * 4;
        *(uint4*)&smg[2 * ABUF + r * BSTR + c4] =
            make_uint4(f2tf(rb[i].x), f2tf(rb[i].y), f2tf(rb[i].z), f2tf(rb[i].w));
    }
    __syncthreads();

    float acc[4][NF][4];
    #pragma unroll
    for (int mi = 0; mi < 4; ++mi)
        #pragma unroll
        for (int ni = 0; ni < NF; ++ni)
            #pragma unroll
            for (int x = 0; x < 4; ++x) acc[mi][ni][x] = 0.0f;

    int cur = 0;
    for (int k0 = 0; k0 < K; k0 += BK) {
        unsigned* Bs = smg + 2 * ABUF + cur * BBUF;
        const unsigned as_addr = sb + (unsigned)(cur * ABUF * 4) +
                                 (unsigned)(wm0 * ASTR * 4) + a_loff;
        const bool more = (k0 + BK) < K;

        if (more) {
            #pragma unroll
            for (int i = 0; i < 4; ++i) {
                int idx = t + 256 * i;
                int r = idx >> 3, c4 = (idx & 7) * 4;
                ra[i] = *(const float4*)&A[(size_t)(m0 + r) * K + k0 + BK + c4];
            }
            #pragma unroll
            for (int i = 0; i < BF4; ++i) {
                int idx = t + 256 * i;
                int r = idx / (BN / 4), c4 = (idx % (BN / 4)) * 4;
                rb[i] = *(const float4*)&W[(size_t)(k0 + BK + r) * N + n0 + c4];
            }
        }

        #pragma unroll
        for (int kk = 0; kk < 4; ++kk) {
            const int kc = kk * 8 + tig;
            unsigned a[4][4];
            #pragma unroll
            for (int mi = 0; mi < 4; ++mi)
                ldsm4(a[mi], as_addr + (unsigned)(mi * 16 * ASTR * 4 + kk * 32));
            #pragma unroll
            for (int ni = 0; ni < NF; ++ni) {
                int n = wn0 + ni * 8 + gid;
                unsigned b0 = Bs[kc * BSTR + n];
                unsigned b1 = Bs[(kc + 4) * BSTR + n];
                #pragma unroll
                for (int mi = 0; mi < 4; ++mi) mma8(acc[mi][ni], a[mi], b0, b1);
            }
        }

        if (more) {
            unsigned* An = smg + (cur ^ 1) * ABUF;
            unsigned* Bn = smg + 2 * ABUF + (cur ^ 1) * BBUF;
            #pragma unroll
            for (int i = 0; i < 4; ++i) {
                int idx = t + 256 * i;
                int r = idx >> 3, c4 = (idx & 7) * 4;
                *(uint4*)&An[r * ASTR + c4] =
                    make_uint4(f2tf(ra[i].x), f2tf(ra[i].y),
                               f2tf(ra[i].z), f2tf(ra[i].w));
            }
            #pragma unroll
            for (int i = 0; i < BF4; ++i) {
                int idx = t + 256 * i;
                int r = idx / (BN / 4), c4 = (idx % (BN / 4)) * 4;
                *(uint4*)&Bn[r * BSTR + c4] =
                    make_uint4(f2tf(rb[i].x), f2tf(rb[i].y),
                               f2tf(rb[i].z), f2tf(rb[i].w));
            }
        }
        __syncthreads();
        cur ^= 1;
    }

    #pragma unroll
    for (int mi = 0; mi < 4; ++mi) {
        int r = m0 + wm0 + mi * 16 + gid;
        #pragma unroll
        for (int ni = 0; ni < NF; ++ni) {
            int c = n0 + wn0 + ni * 8 + 2 * tig;
            float bb0 = bias[c], bb1 = bias[c + 1];
            float o0 = acc[mi][ni][0] + bb0, o1 = acc[mi][ni][1] + bb1;
            float o2 = acc[mi][ni][2] + bb0, o3 = acc[mi][ni][3] + bb1;
            if (rtf) {
                o0 = __uint_as_float(f2tf(o0));
                o1 = __uint_as_float(f2tf(o1));
                o2 = __uint_as_float(f2tf(o2));
                o3 = __uint_as_float(f2tf(o3));
            }
            if (trv) {
                int bb_ = r >> 11, ss = r & (SEQ - 1);
                C[((size_t)(bb_ * DK + c))     * SEQ + ss]     = o0;
                C[((size_t)(bb_ * DK + c + 1)) * SEQ + ss]     = o1;
                C[((size_t)(bb_ * DK + c))     * SEQ + ss + 8] = o2;
                C[((size_t)(bb_ * DK + c + 1)) * SEQ + ss + 8] = o3;
            } else {
                *(float2*)&C[(size_t)r * N + c] = make_float2(o0, o1);
                *(float2*)&C[(size_t)(r + 8) * N + c] = make_float2(o2, o3);
            }
        }
    }
}

// Big projections (Q, O): BN=128
__global__ __launch_bounds__(256)
void gemm_big(const float* __restrict__ A, const float* __restrict__ W,
              const float* __restrict__ bias, float* __restrict__ C,
              int M, int N, int K)
{
    gemm_body<128, 32>(A, W, bias, C, M, N, K,
                       blockIdx.y * 128, blockIdx.x * 128, false, false);
}

// Fused K+V projections: blockIdx.z selects which; V written transposed.
__global__ __launch_bounds__(256)
void gemm_kv(const float* __restrict__ Ak, const float* __restrict__ Wk,
             const float* __restrict__ bk, float* __restrict__ Ck,
             const float* __restrict__ Av, const float* __restrict__ Wv,
             const float* __restrict__ bv, float* __restrict__ Cv)
{
    const bool isv = (blockIdx.z != 0);
    gemm_body<64, 16>(isv ? Av : Ak, isv ? Wv : Wk, isv ? bv : bk,
                      isv ? Cv : Ck, BS_TOK, DK, D_MODEL,
                      blockIdx.y * 128, 0, true, isv);
}

#define GEMM_SMEM_128 ((2 * 128 * 36 + 2 * 32 * 136) * 4)   // 71680
#define GEMM_SMEM_64  ((2 * 128 * 36 + 2 * 32 * 72) * 4)    // 55296

// ---------------------------------------------------------------------------
// Flash attention (MQA, causal), 2 heads/CTA, merged MMA bursts:
// per iteration: barrier -> prefetch -> softmax(j) -> [QK(j+1) + PV(j)] burst.
// Burst j reads K(j+1)@stage (j+1)%2 and V(j)@stage j%2; prefetch at iter j
// writes K(j+2)@stage j%2 and V(j+1)@stage (j+1)%2 (safe after top barrier).
// smem: Ks[2][64][AS], Vts[2][64][AS], Ps[128][AS].
// ---------------------------------------------------------------------------
#define AS 68
#define ATTN_SMEM_TC ((4 * 64 + 128) * AS * 4)   // 104448 B

__global__ __launch_bounds__(256)
void attn_tc(const float* __restrict__ Q, const float* __restrict__ K,
             const float* __restrict__ Vt, float* __restrict__ Ctx)
{
    extern __shared__ unsigned smu[];
    const unsigned sb = (unsigned)__cvta_generic_to_shared(smu);
    unsigned* Ps = smu + 4 * 64 * AS;
    const unsigned ps_base = sb + (unsigned)(4 * 64 * AS * 4);

    const int t = threadIdx.x, lane = t & 31, w = t >> 5;
    const int hw = w & 3;
    const int gid = lane >> 2, tig = lane & 3;
    const int qt = (int)(gridDim.x - 1) - (int)blockIdx.x;  // long blocks first
    const int h = blockIdx.y * 2 + (w >> 2);
    const int b = blockIdx.z;

    const int m4 = lane >> 3, j8 = lane & 7;
    const unsigned a_loff = (unsigned)((((m4 & 1) * 8 + j8) * AS +
                                        (m4 >> 1) * 4) * 4);
    const unsigned b_loff = (unsigned)((((m4 >> 1) * 8 + j8) * AS +
                                        (m4 & 1) * 4) * 4);

    // ---- preloop: prefetch K0 (+K1), V0; stage Q ----
    {
        #pragma unroll
        for (int ld = 0; ld < 4; ++ld) {
            int i = t + 256 * ld;
            int row = i >> 4, c4 = (i & 15) * 4;
            unsigned so = (unsigned)(row * AS + c4) * 4u;
            cpa16(sb + so, K + ((size_t)(b * SEQ + row)) * DK + c4);
            if (qt >= 1)
                cpa16(sb + (64 * AS) * 4u + so,
                      K + ((size_t)(b * SEQ + 64 + row)) * DK + c4);
            cpa16(sb + (2 * 64 * AS) * 4u + so,
                  Vt + ((size_t)(b * DK + row)) * SEQ + c4);
        }
        CP_COMMIT();
    }
    for (int i = t; i < 128 * 16; i += 256) {
        int row = i >> 4, c4 = (i & 15) * 4;
        int hh = blockIdx.y * 2 + (row >> 6);
        int qrow = row & 63;
        float4 v = *(const float4*)
            &Q[((size_t)(b * SEQ + qt * 64 + qrow)) * D_MODEL + hh * DK + c4];
        *(uint4*)&Ps[row * AS + c4] =
            make_uint4(f2tf(0.125f * v.x), f2tf(0.125f * v.y),
                       f2tf(0.125f * v.z), f2tf(0.125f * v.w));
    }
    CP_WAIT0();
    __syncthreads();

    const unsigned ps_warp = ps_base + (unsigned)(16 * w * AS * 4);
    unsigned Qa[8][4];
    #pragma unroll
    for (int kf = 0; kf < 8; ++kf)
        ldsm4(Qa[kf], ps_warp + a_loff + kf * 32);

    float m0 = -INFINITY, m1 = -INFINITY, l0 = 0.0f, l1 = 0.0f;
    float O[8][4], S[8][4];
    #pragma unroll
    for (int nf = 0; nf < 8; ++nf)
        #pragma unroll
        for (int x = 0; x < 4; ++x) { O[nf][x] = 0.0f; S[nf][x] = 0.0f; }

    // ---- QK(0) from stage 0 ----
    #pragma unroll
    for (int kf = 0; kf < 8; ++kf) {
        #pragma unroll
        for (int nfp = 0; nfp < 4; ++nfp) {
            unsigned bb[4];
            ldsm4(bb, sb + (unsigned)(nfp * 16 * AS * 4) + b_loff + kf * 32);
            mma8(S[2 * nfp],     Qa[kf], bb[0], bb[1]);
            mma8(S[2 * nfp + 1], Qa[kf], bb[2], bb[3]);
        }
    }

    for (int j = 0; j <= qt; ++j) {
        CP_WAIT0();        // K(j+1), V(j) landed (committed at iter j-1)
        __syncthreads();   // all warps done with burst j-1 buffer reads

        // ---- prefetch K(j+2) -> stage j%2, V(j+1) -> stage (j+1)%2 ----
        {
            const unsigned ko = (unsigned)((j & 1) * 64 * AS) * 4u;
            const unsigned vo = (unsigned)((2 + ((j + 1) & 1)) * 64 * AS) * 4u;
            #pragma unroll
            for (int ld = 0; ld < 4; ++ld) {
                int i = t + 256 * ld;
                int row = i >> 4, c4 = (i & 15) * 4;
                unsigned so = (unsigned)(row * AS + c4) * 4u;
                if (j + 2 <= qt)
                    cpa16(sb + ko + so,
                          K + ((size_t)(b * SEQ + (j + 2) * 64 + row)) * DK + c4);
                if (j + 1 <= qt)
                    cpa16(sb + vo + so,
                          Vt + ((size_t)(b * DK + row)) * SEQ + (j + 1) * 64 + c4);
            }
            CP_COMMIT();
        }

        // ---- softmax on S (tile j) ----
        if (j == qt) {
            int qr = qt * 64 + 16 * hw + gid;
            #pragma unroll
            for (int nf = 0; nf < 8; ++nf) {
                int c0 = j * 64 + nf * 8 + 2 * tig;
                if (c0     > qr)     S[nf][0] = -INFINITY;
                if (c0 + 1 > qr)     S[nf][1] = -INFINITY;
                if (c0     > qr + 8) S[nf][2] = -INFINITY;
                if (c0 + 1 > qr + 8) S[nf][3] = -INFINITY;
            }
        }
        float mx0 = -INFINITY, mx1 = -INFINITY;
        #pragma unroll
        for (int nf = 0; nf < 8; ++nf) {
            mx0 = fmaxf(mx0, fmaxf(S[nf][0], S[nf][1]));
            mx1 = fmaxf(mx1, fmaxf(S[nf][2], S[nf][3]));
        }
        mx0 = fmaxf(mx0, __shfl_xor_sync(0xffffffffu, mx0, 1));
        mx0 = fmaxf(mx0, __shfl_xor_sync(0xffffffffu, mx0, 2));
        mx1 = fmaxf(mx1, __shfl_xor_sync(0xffffffffu, mx1, 1));
        mx1 = fmaxf(mx1, __shfl_xor_sync(0xffffffffu, mx1, 2));

        float mn0 = fmaxf(m0, mx0), mn1 = fmaxf(m1, mx1);
        float cr0 = __expf(m0 - mn0), cr1 = __expf(m1 - mn1);
        m0 = mn0; m1 = mn1;

        float rs0 = 0.0f, rs1 = 0.0f;
        #pragma unroll
        for (int nf = 0; nf < 8; ++nf) {
            S[nf][0] = __expf(S[nf][0] - mn0);
            S[nf][1] = __expf(S[nf][1] - mn0);
            S[nf][2] = __expf(S[nf][2] - mn1);
            S[nf][3] = __expf(S[nf][3] - mn1);
            rs0 += S[nf][0] + S[nf][1];
            rs1 += S[nf][2] + S[nf][3];
        }
        rs0 += __shfl_xor_sync(0xffffffffu, rs0, 1);
        rs0 += __shfl_xor_sync(0xffffffffu, rs0, 2);
        rs1 += __shfl_xor_sync(0xffffffffu, rs1, 1);
        rs1 += __shfl_xor_sync(0xffffffffu, rs1, 2);
        l0 = l0 * cr0 + rs0;
        l1 = l1 * cr1 + rs1;
        #pragma unroll
        for (int nf = 0; nf < 8; ++nf) {
            O[nf][0] *= cr0; O[nf][1] *= cr0;
            O[nf][2] *= cr1; O[nf][3] *= cr1;
        }

        // ---- P -> smem (warp-private rows), free S for tile j+1 ----
        const int pr = 16 * w + gid;
        #pragma unroll
        for (int nf = 0; nf < 8; ++nf) {
            int pc = nf * 8 + 2 * tig;
            *(uint2*)&Ps[pr * AS + pc] =
                make_uint2(f2tf(S[nf][0]), f2tf(S[nf][1]));
            *(uint2*)&Ps[(pr + 8) * AS + pc] =
                make_uint2(f2tf(S[nf][2]), f2tf(S[nf][3]));
            S[nf][0] = 0.0f; S[nf][1] = 0.0f; S[nf][2] = 0.0f; S[nf][3] = 0.0f;
        }
        __syncwarp();

        // ---- merged burst: QK(j+1) + PV(j) ----
        const unsigned ksb = sb + (unsigned)((((j + 1) & 1)) * 64 * AS * 4);
        const unsigned vtb = sb + (unsigned)((2 + (j & 1)) * 64 * AS * 4);
        if (j < qt) {
            #pragma unroll
            for (int kf = 0; kf < 8; ++kf) {
                unsigned pa[4];
                ldsm4(pa, ps_warp + a_loff + kf * 32);
                #pragma unroll
                for (int nfp = 0; nfp < 4; ++nfp) {
                    unsigned kb[4];
                    ldsm4(kb, ksb + (unsigned)(nfp * 16 * AS * 4) + b_loff
                              + kf * 32);
                    mma8(S[2 * nfp],     Qa[kf], kb[0], kb[1]);
                    mma8(S[2 * nfp + 1], Qa[kf], kb[2], kb[3]);
                }
                #pragma unroll
                for (int nfp = 0; nfp < 4; ++nfp) {
                    unsigned vb[4];
                    ldsm4(vb, vtb + (unsigned)(nfp * 16 * AS * 4) + b_loff
                              + kf * 32);
                    mma8(O[2 * nfp],     pa, vb[0], vb[1]);
                    mma8(O[2 * nfp + 1], pa, vb[2], vb[3]);
                }
            }
        } else {
            #pragma unroll
            for (int kf = 0; kf < 8; ++kf) {
                unsigned pa[4];
                ldsm4(pa, ps_warp + a_loff + kf * 32);
                #pragma unroll
                for (int nfp = 0; nfp < 4; ++nfp) {
                    unsigned vb[4];
                    ldsm4(vb, vtb + (unsigned)(nfp * 16 * AS * 4) + b_loff
                              + kf * 32);
                    mma8(O[2 * nfp],     pa, vb[0], vb[1]);
                    mma8(O[2 * nfp + 1], pa, vb[2], vb[3]);
                }
            }
        }
    }

    // ---- normalize + write context ----
    float inv0 = 1.0f / l0, inv1 = 1.0f / l1;
    int r0 = qt * 64 + 16 * hw + gid;
    #pragma unroll
    for (int nf = 0; nf < 8; ++nf) {
        int c = h * DK + nf * 8 + 2 * tig;
        *(float2*)&Ctx[((size_t)(b * SEQ + r0)) * D_MODEL + c] =
            make_float2(O[nf][0] * inv0, O[nf][1] * inv0);
        *(float2*)&Ctx[((size_t)(b * SEQ + r0 + 8)) * D_MODEL + c] =
            make_float2(O[nf][2] * inv1, O[nf][3] * inv1);
    }
}

// ---------------------------------------------------------------------------
// launch
// ---------------------------------------------------------------------------
extern "C" void kernel_launch(void* const* d_in, const int* in_sizes, int n_in,
                              void* d_out, int out_size)
{
    const float* iq = (const float*)d_in[0];
    const float* ik = (const float*)d_in[1];
    const float* iv = (const float*)d_in[2];
    const float* Wq = (const float*)d_in[3];
    const float* bq = (const float*)d_in[4];
    const float* Wk = (const float*)d_in[5];
    const float* bk = (const float*)d_in[6];
    const float* Wv = (const float*)d_in[7];
    const float* bv = (const float*)d_in[8];
    const float* Wo = (const float*)d_in[9];
    const float* bo = (const float*)d_in[10];
    float* out = (float*)d_out;

    float *pQ, *pK, *pVt, *pCtx;
    cudaGetSymbolAddress((void**)&pQ,   g_Q);
    cudaGetSymbolAddress((void**)&pK,   g_K);
    cudaGetSymbolAddress((void**)&pVt,  g_Vt);
    cudaGetSymbolAddress((void**)&pCtx, g_Ctx);

    cudaFuncSetAttribute((const void*)gemm_big,
                         cudaFuncAttributeMaxDynamicSharedMemorySize,
                         GEMM_SMEM_128);
    cudaFuncSetAttribute((const void*)gemm_kv,
                         cudaFuncAttributeMaxDynamicSharedMemorySize,
                         GEMM_SMEM_64);
    cudaFuncSetAttribute((const void*)attn_tc,
                         cudaFuncAttributeMaxDynamicSharedMemorySize,
                         ATTN_SMEM_TC);

    // Fused K+V projections (z: 0=K row-major, 1=V transposed)
    gemm_kv<<<dim3(1, BS_TOK / 128, 2), 256, GEMM_SMEM_64>>>(
        ik, Wk, bk, pK, iv, Wv, bv, pVt);

    // Q projection
    gemm_big<<<dim3(D_MODEL / 128, BS_TOK / 128), 256, GEMM_SMEM_128>>>(
        iq, Wq, bq, pQ, BS_TOK, D_MODEL, D_MODEL);

    // Attention
    attn_tc<<<dim3(SEQ / 64, NHEADS / 2, BATCH), 256, ATTN_SMEM_TC>>>(
        pQ, pK, pVt, pCtx);

    // Output projection
    gemm_big<<<dim3(D_MODEL / 128, BS_TOK / 128), 256, GEMM_SMEM_128>>>(
        pCtx, Wo, bo, out, BS_TOK, D_MODEL, D_MODEL);
}

// round 8
// speedup vs baseline: 3.8643x; 1.0312x over previous
#include <cuda_runtime.h>
#include <math.h>
#include <stdint.h>

#define D_MODEL 1024
#define NHEADS  16
#define DK      64
#define BATCH   2
#define SEQ     2048
#define BS_TOK  (BATCH * SEQ)   // 4096 tokens

// ---------------------------------------------------------------------------
// Scratch (device globals: no allocation allowed)
// ---------------------------------------------------------------------------
__device__ float g_IQr[BS_TOK * D_MODEL];   // tf32-rounded inputs
__device__ float g_IKr[BS_TOK * D_MODEL];
__device__ float g_IVr[BS_TOK * D_MODEL];
__device__ float g_Wqt[D_MODEL * D_MODEL];  // tf32-rounded, transposed [n][k]
__device__ float g_Wkt[DK * D_MODEL];
__device__ float g_Wvt[DK * D_MODEL];
__device__ float g_Wot[D_MODEL * D_MODEL];
__device__ float g_Q[BS_TOK * D_MODEL];     // pre-scaled (1/8) + tf32-rounded
__device__ float g_K[BS_TOK * DK];          // tf32-rounded, [b*S+s][dk]
__device__ float g_Vt[BS_TOK * DK];         // tf32-rounded, transposed [b][dv][s]
__device__ float g_Ctx[BS_TOK * D_MODEL];   // tf32-rounded

// ---------------------------------------------------------------------------
// tf32 / cp.async / ldmatrix helpers
// ---------------------------------------------------------------------------
__device__ __forceinline__ unsigned f2tf(float x) {
    unsigned r;
    asm("cvt.rna.tf32.f32 %0, %1;" : "=r"(r) : "f"(x));
    return r;
}
__device__ __forceinline__ float f2tff(float x) {
    return __uint_as_float(f2tf(x));
}

__device__ __forceinline__ void cpa16(unsigned dst, const void* src) {
    asm volatile("cp.async.cg.shared.global [%0], [%1], 16;"
                 :: "r"(dst), "l"(src));
}
#define CP_COMMIT() asm volatile("cp.async.commit_group;" ::: "memory")
#define CP_WAIT0()  asm volatile("cp.async.wait_group 0;" ::: "memory")

__device__ __forceinline__ void ldsm4(unsigned* r, unsigned addr) {
    asm volatile("ldmatrix.sync.aligned.m8n8.x4.shared.b16 {%0,%1,%2,%3}, [%4];"
                 : "=r"(r[0]), "=r"(r[1]), "=r"(r[2]), "=r"(r[3]) : "r"(addr));
}

__device__ __forceinline__ void mma8(float* c, const unsigned* a,
                                     unsigned b0, unsigned b1) {
    asm volatile(
        "mma.sync.aligned.m16n8k8.row.col.f32.tf32.tf32.f32 "
        "{%0,%1,%2,%3}, {%4,%5,%6,%7}, {%8,%9}, {%0,%1,%2,%3};"
        : "+f"(c[0]), "+f"(c[1]), "+f"(c[2]), "+f"(c[3])
        : "r"(a[0]), "r"(a[1]), "r"(a[2]), "r"(a[3]), "r"(b0), "r"(b1));
}

// ---------------------------------------------------------------------------
// Prep: round the three inputs to tf32 bits (elementwise)
// ---------------------------------------------------------------------------
__global__ void round3(const float* __restrict__ a, const float* __restrict__ b,
                       const float* __restrict__ c, float* __restrict__ oa,
                       float* __restrict__ ob, float* __restrict__ oc, int n4)
{
    for (int i = blockIdx.x * blockDim.x + threadIdx.x; i < n4;
         i += gridDim.x * blockDim.x) {
        float4 v = ((const float4*)a)[i];
        ((float4*)oa)[i] = make_float4(f2tff(v.x), f2tff(v.y), f2tff(v.z), f2tff(v.w));
        v = ((const float4*)b)[i];
        ((float4*)ob)[i] = make_float4(f2tff(v.x), f2tff(v.y), f2tff(v.z), f2tff(v.w));
        v = ((const float4*)c)[i];
        ((float4*)oc)[i] = make_float4(f2tff(v.x), f2tff(v.y), f2tff(v.z), f2tff(v.w));
    }
}

// Prep: Wt[n][k] = rna(W[k][n]); K x N -> N x K. block (32,8), grid (N/32, K/32)
__global__ void trW(const float* __restrict__ W, float* __restrict__ Wt,
                    int K, int N)
{
    __shared__ float tl[32][33];
    int bx = blockIdx.x * 32, by = blockIdx.y * 32;
    int tx = threadIdx.x, ty = threadIdx.y;
    #pragma unroll
    for (int i = 0; i < 4; ++i)
        tl[ty + i * 8][tx] = f2tff(W[(size_t)(by + ty + i * 8) * N + bx + tx]);
    __syncthreads();
    #pragma unroll
    for (int i = 0; i < 4; ++i)
        Wt[(size_t)(bx + ty + i * 8) * K + by + tx] = tl[tx][ty + i * 8];
}

// ---------------------------------------------------------------------------
// Tensor-core GEMM, cp.async double-buffered, all fragments via ldmatrix.
// A [M,K] row-major (tf32 bits), Wt [N,K] row-major (tf32 bits).
// smem: As[2][128][36], Bs[2][BN][36]. OMODE: 0 plain, 1 rtf, 2 rtf*0.125,
// 3 rtf + transposed V write.
// ---------------------------------------------------------------------------
template<int BN, int WN, int OMODE>
__device__ __forceinline__
void gemm_body(const float* __restrict__ A, const float* __restrict__ Wt,
               const float* __restrict__ bias, float* __restrict__ C,
               int N, int K, int m0, int n0)
{
    constexpr int ASTR = 36;
    constexpr int ABUF = 128 * ASTR;
    constexpr int BBUF = BN * ASTR;
    constexpr int NF = WN / 8;
    constexpr int ACH = (128 * 8) / 256;   // A chunks per thread = 4
    constexpr int BCH = (BN * 8) / 256;    // B chunks per thread
    extern __shared__ unsigned smg[];
    const unsigned sb = (unsigned)__cvta_generic_to_shared(smg);

    const int t = threadIdx.x, lane = t & 31, wp = t >> 5;
    const int wm0 = (wp >> 2) * 64, wn0 = (wp & 3) * WN;
    const int gid = lane >> 2, tig = lane & 3;

    const int m4 = lane >> 3, j8 = lane & 7;
    const unsigned a_loff = (unsigned)((((m4 & 1) * 8 + j8) * ASTR +
                                        (m4 >> 1) * 4) * 4);
    const unsigned b_loff = (unsigned)((((m4 >> 1) * 8 + j8) * ASTR +
                                        (m4 & 1) * 4) * 4);

    // ---- prologue: stage tile 0 into buffers 0 ----
    #pragma unroll
    for (int i = 0; i < ACH; ++i) {
        int idx = t + 256 * i;
        int r = idx >> 3, c4 = (idx & 7) * 4;
        cpa16(sb + (unsigned)((r * ASTR + c4) * 4),
              A + (size_t)(m0 + r) * K + c4);
    }
    #pragma unroll
    for (int i = 0; i < BCH; ++i) {
        int idx = t + 256 * i;
        int r = idx >> 3, c4 = (idx & 7) * 4;
        cpa16(sb + (unsigned)((2 * ABUF + r * ASTR + c4) * 4),
              Wt + (size_t)(n0 + r) * K + c4);
    }
    CP_COMMIT();

    float acc[4][NF][4];
    #pragma unroll
    for (int mi = 0; mi < 4; ++mi)
        #pragma unroll
        for (int ni = 0; ni < NF; ++ni)
            #pragma unroll
            for (int x = 0; x < 4; ++x) acc[mi][ni][x] = 0.0f;

    int cur = 0;
    for (int k0 = 0; k0 < K; k0 += 32) {
        CP_WAIT0();
        __syncthreads();

        if (k0 + 32 < K) {
            const unsigned ao = (unsigned)((cur ^ 1) * ABUF * 4);
            const unsigned bo = (unsigned)((2 * ABUF + (cur ^ 1) * BBUF) * 4);
            #pragma unroll
            for (int i = 0; i < ACH; ++i) {
                int idx = t + 256 * i;
                int r = idx >> 3, c4 = (idx & 7) * 4;
                cpa16(sb + ao + (unsigned)((r * ASTR + c4) * 4),
                      A + (size_t)(m0 + r) * K + k0 + 32 + c4);
            }
            #pragma unroll
            for (int i = 0; i < BCH; ++i) {
                int idx = t + 256 * i;
                int r = idx >> 3, c4 = (idx & 7) * 4;
                cpa16(sb + bo + (unsigned)((r * ASTR + c4) * 4),
                      Wt + (size_t)(n0 + r) * K + k0 + 32 + c4);
            }
            CP_COMMIT();
        }

        const unsigned asb = sb + (unsigned)(cur * ABUF * 4) +
                             (unsigned)(wm0 * ASTR * 4) + a_loff;
        const unsigned bsb = sb + (unsigned)((2 * ABUF + cur * BBUF) * 4) +
                             (unsigned)(wn0 * ASTR * 4) + b_loff;

        #pragma unroll
        for (int kk = 0; kk < 4; ++kk) {
            unsigned a[4][4];
            #pragma unroll
            for (int mi = 0; mi < 4; ++mi)
                ldsm4(a[mi], asb + (unsigned)(mi * 16 * ASTR * 4 + kk * 32));
            #pragma unroll
            for (int nfp = 0; nfp < NF / 2; ++nfp) {
                unsigned bb[4];
                ldsm4(bb, bsb + (unsigned)(nfp * 16 * ASTR * 4 + kk * 32));
                #pragma unroll
                for (int mi = 0; mi < 4; ++mi) {
                    mma8(acc[mi][2 * nfp],     a[mi], bb[0], bb[1]);
                    mma8(acc[mi][2 * nfp + 1], a[mi], bb[2], bb[3]);
                }
            }
        }
        cur ^= 1;
    }

    // ---- epilogue ----
    #pragma unroll
    for (int mi = 0; mi < 4; ++mi) {
        int r = m0 + wm0 + mi * 16 + gid;
        #pragma unroll
        for (int ni = 0; ni < NF; ++ni) {
            int c = n0 + wn0 + ni * 8 + 2 * tig;
            float bb0 = bias[c], bb1 = bias[c + 1];
            float o0 = acc[mi][ni][0] + bb0, o1 = acc[mi][ni][1] + bb1;
            float o2 = acc[mi][ni][2] + bb0, o3 = acc[mi][ni][3] + bb1;
            if (OMODE == 2) {
                o0 = f2tff(0.125f * o0); o1 = f2tff(0.125f * o1);
                o2 = f2tff(0.125f * o2); o3 = f2tff(0.125f * o3);
            } else if (OMODE == 1 || OMODE == 3) {
                o0 = f2tff(o0); o1 = f2tff(o1);
                o2 = f2tff(o2); o3 = f2tff(o3);
            }
            if (OMODE == 3) {
                int bb_ = r >> 11, ss = r & (SEQ - 1);
                C[((size_t)(bb_ * DK + c))     * SEQ + ss]     = o0;
                C[((size_t)(bb_ * DK + c + 1)) * SEQ + ss]     = o1;
                C[((size_t)(bb_ * DK + c))     * SEQ + ss + 8] = o2;
                C[((size_t)(bb_ * DK + c + 1)) * SEQ + ss + 8] = o3;
            } else {
                *(float2*)&C[(size_t)r * N + c] = make_float2(o0, o1);
                *(float2*)&C[(size_t)(r + 8) * N + c] = make_float2(o2, o3);
            }
        }
    }
}

__global__ __launch_bounds__(256)
void gemm_q(const float* __restrict__ A, const float* __restrict__ Wt,
            const float* __restrict__ bias, float* __restrict__ C)
{
    gemm_body<128, 32, 2>(A, Wt, bias, C, D_MODEL, D_MODEL,
                          blockIdx.y * 128, blockIdx.x * 128);
}

__global__ __launch_bounds__(256)
void gemm_o(const float* __restrict__ A, const float* __restrict__ Wt,
            const float* __restrict__ bias, float* __restrict__ C)
{
    gemm_body<128, 32, 0>(A, Wt, bias, C, D_MODEL, D_MODEL,
                          blockIdx.y * 128, blockIdx.x * 128);
}

__global__ __launch_bounds__(256)
void gemm_kv(const float* __restrict__ Ak, const float* __restrict__ Wkt,
             const float* __restrict__ bk, float* __restrict__ Ck,
             const float* __restrict__ Av, const float* __restrict__ Wvt,
             const float* __restrict__ bv, float* __restrict__ Cv)
{
    if (blockIdx.z == 0)
        gemm_body<64, 16, 1>(Ak, Wkt, bk, Ck, DK, D_MODEL,
                             blockIdx.y * 128, 0);
    else
        gemm_body<64, 16, 3>(Av, Wvt, bv, Cv, DK, D_MODEL,
                             blockIdx.y * 128, 0);
}

#define GEMM_SMEM_128 ((2 * 128 * 36 + 2 * 128 * 36) * 4)   // 73728
#define GEMM_SMEM_64  ((2 * 128 * 36 + 2 * 64 * 36) * 4)    // 55296

// ---------------------------------------------------------------------------
// Flash attention (MQA, causal), 2 heads/CTA, merged MMA bursts, cp.async
// staging for Q, K and Vt (all pre-rounded/pre-scaled tf32 bits).
// Per iter: wait+barrier -> prefetch -> softmax(j) -> [QK(j+1) + PV(j)].
// smem: Ks[2][64][AS], Vts[2][64][AS], Ps[128][AS].
// ---------------------------------------------------------------------------
#define AS 68
#define ATTN_SMEM_TC ((4 * 64 + 128) * AS * 4)   // 104448 B

__global__ __launch_bounds__(256)
void attn_tc(const float* __restrict__ Q, const float* __restrict__ K,
             const float* __restrict__ Vt, float* __restrict__ Ctx)
{
    extern __shared__ unsigned smu[];
    const unsigned sb = (unsigned)__cvta_generic_to_shared(smu);
    unsigned* Ps = smu + 4 * 64 * AS;
    const unsigned ps_base = sb + (unsigned)(4 * 64 * AS * 4);

    const int t = threadIdx.x, lane = t & 31, w = t >> 5;
    const int hw = w & 3;
    const int gid = lane >> 2, tig = lane & 3;
    const int qt = (int)(gridDim.x - 1) - (int)blockIdx.x;  // long blocks first
    const int h = blockIdx.y * 2 + (w >> 2);
    const int b = blockIdx.z;

    const int m4 = lane >> 3, j8 = lane & 7;
    const unsigned a_loff = (unsigned)((((m4 & 1) * 8 + j8) * AS +
                                        (m4 >> 1) * 4) * 4);
    const unsigned b_loff = (unsigned)((((m4 >> 1) * 8 + j8) * AS +
                                        (m4 & 1) * 4) * 4);

    // ---- preloop: cp.async K0 (+K1), V0, and Q (both heads) ----
    {
        #pragma unroll
        for (int ld = 0; ld < 4; ++ld) {
            int i = t + 256 * ld;
            int row = i >> 4, c4 = (i & 15) * 4;
            unsigned so = (unsigned)(row * AS + c4) * 4u;
            cpa16(sb + so, K + ((size_t)(b * SEQ + row)) * DK + c4);
            if (qt >= 1)
                cpa16(sb + (64 * AS) * 4u + so,
                      K + ((size_t)(b * SEQ + 64 + row)) * DK + c4);
            cpa16(sb + (2 * 64 * AS) * 4u + so,
                  Vt + ((size_t)(b * DK + row)) * SEQ + c4);
        }
        #pragma unroll
        for (int ld = 0; ld < 8; ++ld) {
            int i = t + 256 * ld;
            int row = i >> 4, c4 = (i & 15) * 4;
            int hh = blockIdx.y * 2 + (row >> 6);
            int qrow = row & 63;
            cpa16(ps_base + (unsigned)(row * AS + c4) * 4u,
                  Q + ((size_t)(b * SEQ + qt * 64 + qrow)) * D_MODEL
                    + hh * DK + c4);
        }
        CP_COMMIT();
    }
    CP_WAIT0();
    __syncthreads();

    const unsigned ps_warp = ps_base + (unsigned)(16 * w * AS * 4);
    unsigned Qa[8][4];
    #pragma unroll
    for (int kf = 0; kf < 8; ++kf)
        ldsm4(Qa[kf], ps_warp + a_loff + kf * 32);

    float m0 = -INFINITY, m1 = -INFINITY, l0 = 0.0f, l1 = 0.0f;
    float O[8][4], S[8][4];
    #pragma unroll
    for (int nf = 0; nf < 8; ++nf)
        #pragma unroll
        for (int x = 0; x < 4; ++x) { O[nf][x] = 0.0f; S[nf][x] = 0.0f; }

    // ---- QK(0) from stage 0 ----
    #pragma unroll
    for (int kf = 0; kf < 8; ++kf) {
        #pragma unroll
        for (int nfp = 0; nfp < 4; ++nfp) {
            unsigned bb[4];
            ldsm4(bb, sb + (unsigned)(nfp * 16 * AS * 4) + b_loff + kf * 32);
            mma8(S[2 * nfp],     Qa[kf], bb[0], bb[1]);
            mma8(S[2 * nfp + 1], Qa[kf], bb[2], bb[3]);
        }
    }

    for (int j = 0; j <= qt; ++j) {
        CP_WAIT0();
        __syncthreads();

        // ---- prefetch K(j+2) -> stage j%2, V(j+1) -> stage (j+1)%2 ----
        {
            const unsigned ko = (unsigned)((j & 1) * 64 * AS) * 4u;
            const unsigned vo = (unsigned)((2 + ((j + 1) & 1)) * 64 * AS) * 4u;
            #pragma unroll
            for (int ld = 0; ld < 4; ++ld) {
                int i = t + 256 * ld;
                int row = i >> 4, c4 = (i & 15) * 4;
                unsigned so = (unsigned)(row * AS + c4) * 4u;
                if (j + 2 <= qt)
                    cpa16(sb + ko + so,
                          K + ((size_t)(b * SEQ + (j + 2) * 64 + row)) * DK + c4);
                if (j + 1 <= qt)
                    cpa16(sb + vo + so,
                          Vt + ((size_t)(b * DK + row)) * SEQ + (j + 1) * 64 + c4);
            }
            CP_COMMIT();
        }

        // ---- softmax on S (tile j) ----
        if (j == qt) {
            int qr = qt * 64 + 16 * hw + gid;
            #pragma unroll
            for (int nf = 0; nf < 8; ++nf) {
                int c0 = j * 64 + nf * 8 + 2 * tig;
                if (c0     > qr)     S[nf][0] = -INFINITY;
                if (c0 + 1 > qr)     S[nf][1] = -INFINITY;
                if (c0     > qr + 8) S[nf][2] = -INFINITY;
                if (c0 + 1 > qr + 8) S[nf][3] = -INFINITY;
            }
        }
        float mx0 = -INFINITY, mx1 = -INFINITY;
        #pragma unroll
        for (int nf = 0; nf < 8; ++nf) {
            mx0 = fmaxf(mx0, fmaxf(S[nf][0], S[nf][1]));
            mx1 = fmaxf(mx1, fmaxf(S[nf][2], S[nf][3]));
        }
        mx0 = fmaxf(mx0, __shfl_xor_sync(0xffffffffu, mx0, 1));
        mx0 = fmaxf(mx0, __shfl_xor_sync(0xffffffffu, mx0, 2));
        mx1 = fmaxf(mx1, __shfl_xor_sync(0xffffffffu, mx1, 1));
        mx1 = fmaxf(mx1, __shfl_xor_sync(0xffffffffu, mx1, 2));

        float mn0 = fmaxf(m0, mx0), mn1 = fmaxf(m1, mx1);
        float cr0 = __expf(m0 - mn0), cr1 = __expf(m1 - mn1);
        m0 = mn0; m1 = mn1;

        float rs0 = 0.0f, rs1 = 0.0f;
        #pragma unroll
        for (int nf = 0; nf < 8; ++nf) {
            S[nf][0] = __expf(S[nf][0] - mn0);
            S[nf][1] = __expf(S[nf][1] - mn0);
            S[nf][2] = __expf(S[nf][2] - mn1);
            S[nf][3] = __expf(S[nf][3] - mn1);
            rs0 += S[nf][0] + S[nf][1];
            rs1 += S[nf][2] + S[nf][3];
        }
        rs0 += __shfl_xor_sync(0xffffffffu, rs0, 1);
        rs0 += __shfl_xor_sync(0xffffffffu, rs0, 2);
        rs1 += __shfl_xor_sync(0xffffffffu, rs1, 1);
        rs1 += __shfl_xor_sync(0xffffffffu, rs1, 2);
        l0 = l0 * cr0 + rs0;
        l1 = l1 * cr1 + rs1;
        #pragma unroll
        for (int nf = 0; nf < 8; ++nf) {
            O[nf][0] *= cr0; O[nf][1] *= cr0;
            O[nf][2] *= cr1; O[nf][3] *= cr1;
        }

        // ---- P -> smem (warp-private rows), free S for tile j+1 ----
        const int pr = 16 * w + gid;
        #pragma unroll
        for (int nf = 0; nf < 8; ++nf) {
            int pc = nf * 8 + 2 * tig;
            *(uint2*)&Ps[pr * AS + pc] =
                make_uint2(f2tf(S[nf][0]), f2tf(S[nf][1]));
            *(uint2*)&Ps[(pr + 8) * AS + pc] =
                make_uint2(f2tf(S[nf][2]), f2tf(S[nf][3]));
            S[nf][0] = 0.0f; S[nf][1] = 0.0f; S[nf][2] = 0.0f; S[nf][3] = 0.0f;
        }
        __syncwarp();

        // ---- merged burst: QK(j+1) + PV(j) ----
        const unsigned ksb = sb + (unsigned)((((j + 1) & 1)) * 64 * AS * 4);
        const unsigned vtb = sb + (unsigned)((2 + (j & 1)) * 64 * AS * 4);
        if (j < qt) {
            #pragma unroll
            for (int kf = 0; kf < 8; ++kf) {
                unsigned pa[4];
                ldsm4(pa, ps_warp + a_loff + kf * 32);
                #pragma unroll
                for (int nfp = 0; nfp < 4; ++nfp) {
                    unsigned kb[4];
                    ldsm4(kb, ksb + (unsigned)(nfp * 16 * AS * 4) + b_loff
                              + kf * 32);
                    mma8(S[2 * nfp],     Qa[kf], kb[0], kb[1]);
                    mma8(S[2 * nfp + 1], Qa[kf], kb[2], kb[3]);
                }
                #pragma unroll
                for (int nfp = 0; nfp < 4; ++nfp) {
                    unsigned vb[4];
                    ldsm4(vb, vtb + (unsigned)(nfp * 16 * AS * 4) + b_loff
                              + kf * 32);
                    mma8(O[2 * nfp],     pa, vb[0], vb[1]);
                    mma8(O[2 * nfp + 1], pa, vb[2], vb[3]);
                }
            }
        } else {
            #pragma unroll
            for (int kf = 0; kf < 8; ++kf) {
                unsigned pa[4];
                ldsm4(pa, ps_warp + a_loff + kf * 32);
                #pragma unroll
                for (int nfp = 0; nfp < 4; ++nfp) {
                    unsigned vb[4];
                    ldsm4(vb, vtb + (unsigned)(nfp * 16 * AS * 4) + b_loff
                              + kf * 32);
                    mma8(O[2 * nfp],     pa, vb[0], vb[1]);
                    mma8(O[2 * nfp + 1], pa, vb[2], vb[3]);
                }
            }
        }
    }

    // ---- normalize + write context (tf32-rounded for the O projection) ----
    float inv0 = 1.0f / l0, inv1 = 1.0f / l1;
    int r0 = qt * 64 + 16 * hw + gid;
    #pragma unroll
    for (int nf = 0; nf < 8; ++nf) {
        int c = h * DK + nf * 8 + 2 * tig;
        *(float2*)&Ctx[((size_t)(b * SEQ + r0)) * D_MODEL + c] =
            make_float2(f2tff(O[nf][0] * inv0), f2tff(O[nf][1] * inv0));
        *(float2*)&Ctx[((size_t)(b * SEQ + r0 + 8)) * D_MODEL + c] =
            make_float2(f2tff(O[nf][2] * inv1), f2tff(O[nf][3] * inv1));
    }
}

// ---------------------------------------------------------------------------
// launch
// ---------------------------------------------------------------------------
extern "C" void kernel_launch(void* const* d_in, const int* in_sizes, int n_in,
                              void* d_out, int out_size)
{
    const float* iq = (const float*)d_in[0];
    const float* ik = (const float*)d_in[1];
    const float* iv = (const float*)d_in[2];
    const float* Wq = (const float*)d_in[3];
    const float* bq = (const float*)d_in[4];
    const float* Wk = (const float*)d_in[5];
    const float* bk = (const float*)d_in[6];
    const float* Wv = (const float*)d_in[7];
    const float* bv = (const float*)d_in[8];
    const float* Wo = (const float*)d_in[9];
    const float* bo = (const float*)d_in[10];
    float* out = (float*)d_out;

    float *pIQ, *pIK, *pIV, *pWqt, *pWkt, *pWvt, *pWot;
    float *pQ, *pK, *pVt, *pCtx;
    cudaGetSymbolAddress((void**)&pIQ,  g_IQr);
    cudaGetSymbolAddress((void**)&pIK,  g_IKr);
    cudaGetSymbolAddress((void**)&pIV,  g_IVr);
    cudaGetSymbolAddress((void**)&pWqt, g_Wqt);
    cudaGetSymbolAddress((void**)&pWkt, g_Wkt);
    cudaGetSymbolAddress((void**)&pWvt, g_Wvt);
    cudaGetSymbolAddress((void**)&pWot, g_Wot);
    cudaGetSymbolAddress((void**)&pQ,   g_Q);
    cudaGetSymbolAddress((void**)&pK,   g_K);
    cudaGetSymbolAddress((void**)&pVt,  g_Vt);
    cudaGetSymbolAddress((void**)&pCtx, g_Ctx);

    cudaFuncSetAttribute((const void*)gemm_q,
                         cudaFuncAttributeMaxDynamicSharedMemorySize,
                         GEMM_SMEM_128);
    cudaFuncSetAttribute((const void*)gemm_o,
                         cudaFuncAttributeMaxDynamicSharedMemorySize,
                         GEMM_SMEM_128);
    cudaFuncSetAttribute((const void*)gemm_kv,
                         cudaFuncAttributeMaxDynamicSharedMemorySize,
                         GEMM_SMEM_64);
    cudaFuncSetAttribute((const void*)attn_tc,
                         cudaFuncAttributeMaxDynamicSharedMemorySize,
                         ATTN_SMEM_TC);

    // ---- prep: round inputs, round+transpose weights ----
    round3<<<1024, 256>>>(iq, ik, iv, pIQ, pIK, pIV,
                          BS_TOK * D_MODEL / 4);
    trW<<<dim3(D_MODEL / 32, D_MODEL / 32), dim3(32, 8)>>>(Wq, pWqt,
                                                           D_MODEL, D_MODEL);
    trW<<<dim3(DK / 32, D_MODEL / 32), dim3(32, 8)>>>(Wk, pWkt, D_MODEL, DK);
    trW<<<dim3(DK / 32, D_MODEL / 32), dim3(32, 8)>>>(Wv, pWvt, D_MODEL, DK);
    trW<<<dim3(D_MODEL / 32, D_MODEL / 32), dim3(32, 8)>>>(Wo, pWot,
                                                           D_MODEL, D_MODEL);

    // ---- K+V projections (z: 0=K row-major, 1=V transposed) ----
    gemm_kv<<<dim3(1, BS_TOK / 128, 2), 256, GEMM_SMEM_64>>>(
        pIK, pWkt, bk, pK, pIV, pWvt, bv, pVt);

    // ---- Q projection (output pre-scaled + rounded) ----
    gemm_q<<<dim3(D_MODEL / 128, BS_TOK / 128), 256, GEMM_SMEM_128>>>(
        pIQ, pWqt, bq, pQ);

    // ---- attention ----
    attn_tc<<<dim3(SEQ / 64, NHEADS / 2, BATCH), 256, ATTN_SMEM_TC>>>(
        pQ, pK, pVt, pCtx);

    // ---- output projection ----
    gemm_o<<<dim3(D_MODEL / 128, BS_TOK / 128), 256, GEMM_SMEM_128>>>(
        pCtx, pWot, bo, out);
}